// round 1
// baseline (speedup 1.0000x reference)
#include <cuda_runtime.h>
#include <math.h>

#define EDIM 128
#define NH 8
#define NB 2
#define TS 4096
#define HEDIM 1024   // NH*EDIM
#define BT 8192      // NB*TS

// Scratch (device globals; no runtime allocation)
__device__ float g_Qp[(size_t)BT * HEDIM];
__device__ float g_Kp[(size_t)BT * HEDIM];
__device__ float g_Vp[(size_t)BT * HEDIM];
__device__ float g_Op[(size_t)BT * HEDIM];

// ---------------------------------------------------------------------------
// Generic tiled fp32 GEMM: C[M,N] = A[M,K] @ B[K,N]. BM=BN=64, BK=32,
// 256 threads, 4x4 per thread. Assumes M%64==0, N%64==0, K%32==0.
// ---------------------------------------------------------------------------
__global__ __launch_bounds__(256) void gemm_k(const float* __restrict__ A,
                                              const float* __restrict__ B,
                                              float* __restrict__ C,
                                              int M, int N, int K) {
    __shared__ float sA[64][33];
    __shared__ float sB[32][64];
    const int tid = threadIdx.x;
    const int tx = tid & 15, ty = tid >> 4;
    const int n0 = blockIdx.x << 6, m0 = blockIdx.y << 6;
    float acc[4][4] = {};

    for (int k0 = 0; k0 < K; k0 += 32) {
#pragma unroll
        for (int i = 0; i < 8; ++i) {
            int idx = tid + (i << 8);
            int r = idx >> 5, c = idx & 31;
            sA[r][c] = A[(size_t)(m0 + r) * K + (k0 + c)];
        }
#pragma unroll
        for (int i = 0; i < 8; ++i) {
            int idx = tid + (i << 8);
            int r = idx >> 6, c = idx & 63;
            sB[r][c] = B[(size_t)(k0 + r) * N + (n0 + c)];
        }
        __syncthreads();
#pragma unroll
        for (int kk = 0; kk < 32; ++kk) {
            float a0 = sA[(ty << 2) + 0][kk];
            float a1 = sA[(ty << 2) + 1][kk];
            float a2 = sA[(ty << 2) + 2][kk];
            float a3 = sA[(ty << 2) + 3][kk];
            float4 b4 = *(const float4*)&sB[kk][tx << 2];
            acc[0][0] += a0 * b4.x; acc[0][1] += a0 * b4.y;
            acc[0][2] += a0 * b4.z; acc[0][3] += a0 * b4.w;
            acc[1][0] += a1 * b4.x; acc[1][1] += a1 * b4.y;
            acc[1][2] += a1 * b4.z; acc[1][3] += a1 * b4.w;
            acc[2][0] += a2 * b4.x; acc[2][1] += a2 * b4.y;
            acc[2][2] += a2 * b4.z; acc[2][3] += a2 * b4.w;
            acc[3][0] += a3 * b4.x; acc[3][1] += a3 * b4.y;
            acc[3][2] += a3 * b4.z; acc[3][3] += a3 * b4.w;
        }
        __syncthreads();
    }
#pragma unroll
    for (int i = 0; i < 4; ++i)
#pragma unroll
        for (int j = 0; j < 4; ++j)
            C[(size_t)(m0 + (ty << 2) + i) * N + n0 + (tx << 2) + j] = acc[i][j];
}

// ---------------------------------------------------------------------------
// Flash attention, fp32. One CTA = (64 queries) x (one b,h). 256 threads
// arranged 16x16; each thread owns S fragment 4x4 and O fragment 4x8.
// Q/K stored transposed in smem -> float4 broadcast reads in the S loop.
// ---------------------------------------------------------------------------
#define BM 64
#define BN 64
#define QK_STR 68  // row stride of transposed Q/K tiles (multiple of 4, !=0 mod 32)
#define P_STR 68

#define SM_QT 0
#define SM_KT (EDIM * QK_STR)                 // 8704
#define SM_V  (SM_KT + EDIM * QK_STR)         // 17408
#define SM_P  (SM_V + BN * EDIM)              // 25600
#define SM_FLOATS (SM_P + BM * P_STR)         // 29952
#define SM_BYTES (SM_FLOATS * 4)              // 119808

__global__ __launch_bounds__(256) void flash_attn(const float* __restrict__ Qg,
                                                  const float* __restrict__ Kg,
                                                  const float* __restrict__ Vg,
                                                  float* __restrict__ Og) {
    extern __shared__ float smem_f[];
    float* sQT = smem_f + SM_QT;
    float* sKT = smem_f + SM_KT;
    float* sV  = smem_f + SM_V;
    float* sP  = smem_f + SM_P;

    const int tid = threadIdx.x;
    const int tx = tid & 15, ty = tid >> 4;
    const int h = blockIdx.y, b = blockIdx.z;
    const int q0 = blockIdx.x * BM;
    const float scale = 0.08838834764831845f;  // 1/sqrt(128)

    // base pointer for (b,h): element (t,e) at t*HEDIM + e
    const size_t bh_off = (size_t)b * TS * HEDIM + (size_t)h * EDIM;
    const float* Qbh = Qg + bh_off;
    const float* Kbh = Kg + bh_off;
    const float* Vbh = Vg + bh_off;
    float* Obh = Og + bh_off;

    // Load Q tile transposed (pre-scaled): sQT[e][r]
    for (int idx = tid; idx < BM * EDIM; idx += 256) {
        int r = idx >> 7, e = idx & 127;
        sQT[e * QK_STR + r] = Qbh[(size_t)(q0 + r) * HEDIM + e] * scale;
    }

    float m_i[4], l_i[4];
    float o_acc[4][8];
#pragma unroll
    for (int i = 0; i < 4; ++i) {
        m_i[i] = -INFINITY;
        l_i[i] = 0.f;
#pragma unroll
        for (int j = 0; j < 8; ++j) o_acc[i][j] = 0.f;
    }

    for (int kv0 = 0; kv0 < TS; kv0 += BN) {
        // Load K (transposed) and V tiles
        for (int idx = tid; idx < BN * EDIM; idx += 256) {
            int r = idx >> 7, e = idx & 127;
            sKT[e * QK_STR + r] = Kbh[(size_t)(kv0 + r) * HEDIM + e];
        }
        for (int idx = tid; idx < BN * EDIM; idx += 256) {
            int r = idx >> 7, e = idx & 127;
            sV[r * EDIM + e] = Vbh[(size_t)(kv0 + r) * HEDIM + e];
        }
        __syncthreads();

        // S = (Q*scale) @ K^T  fragment (4x4 per thread)
        float s[4][4] = {};
#pragma unroll 8
        for (int kk = 0; kk < EDIM; ++kk) {
            float4 qa = *(const float4*)&sQT[kk * QK_STR + (ty << 2)];
            float4 kb = *(const float4*)&sKT[kk * QK_STR + (tx << 2)];
            s[0][0] += qa.x * kb.x; s[0][1] += qa.x * kb.y;
            s[0][2] += qa.x * kb.z; s[0][3] += qa.x * kb.w;
            s[1][0] += qa.y * kb.x; s[1][1] += qa.y * kb.y;
            s[1][2] += qa.y * kb.z; s[1][3] += qa.y * kb.w;
            s[2][0] += qa.z * kb.x; s[2][1] += qa.z * kb.y;
            s[2][2] += qa.z * kb.z; s[2][3] += qa.z * kb.w;
            s[3][0] += qa.w * kb.x; s[3][1] += qa.w * kb.y;
            s[3][2] += qa.w * kb.z; s[3][3] += qa.w * kb.w;
        }

        // Online softmax per row (rows are ty*4+i, spread over 16 lanes in tx)
#pragma unroll
        for (int i = 0; i < 4; ++i) {
            float lm = fmaxf(fmaxf(s[i][0], s[i][1]), fmaxf(s[i][2], s[i][3]));
#pragma unroll
            for (int off = 8; off; off >>= 1)
                lm = fmaxf(lm, __shfl_xor_sync(0xffffffffu, lm, off));
            float mn = fmaxf(m_i[i], lm);
            float alpha = __expf(m_i[i] - mn);
            float psum = 0.f;
#pragma unroll
            for (int j = 0; j < 4; ++j) {
                float p = __expf(s[i][j] - mn);
                s[i][j] = p;
                psum += p;
            }
#pragma unroll
            for (int off = 8; off; off >>= 1)
                psum += __shfl_xor_sync(0xffffffffu, psum, off);
            l_i[i] = l_i[i] * alpha + psum;
            m_i[i] = mn;
#pragma unroll
            for (int j = 0; j < 8; ++j) o_acc[i][j] *= alpha;
        }

        // Stage P to smem
#pragma unroll
        for (int i = 0; i < 4; ++i) {
            float4 p4 = make_float4(s[i][0], s[i][1], s[i][2], s[i][3]);
            *(float4*)&sP[((ty << 2) + i) * P_STR + (tx << 2)] = p4;
        }
        __syncthreads();

        // O += P @ V   (cols tx*8 .. tx*8+7)
        for (int kk = 0; kk < BN; kk += 4) {
            float pr[4][4];
#pragma unroll
            for (int i = 0; i < 4; ++i)
                *(float4*)pr[i] = *(const float4*)&sP[((ty << 2) + i) * P_STR + kk];
#pragma unroll
            for (int u = 0; u < 4; ++u) {
                float4 va = *(const float4*)&sV[(kk + u) * EDIM + (tx << 3)];
                float4 vb = *(const float4*)&sV[(kk + u) * EDIM + (tx << 3) + 4];
#pragma unroll
                for (int i = 0; i < 4; ++i) {
                    float p = pr[i][u];
                    o_acc[i][0] += p * va.x; o_acc[i][1] += p * va.y;
                    o_acc[i][2] += p * va.z; o_acc[i][3] += p * va.w;
                    o_acc[i][4] += p * vb.x; o_acc[i][5] += p * vb.y;
                    o_acc[i][6] += p * vb.z; o_acc[i][7] += p * vb.w;
                }
            }
        }
        __syncthreads();
    }

    // Normalize + write O in [b,t,h,e] layout
#pragma unroll
    for (int i = 0; i < 4; ++i) {
        float inv = 1.f / l_i[i];
        size_t row = (size_t)(q0 + (ty << 2) + i) * HEDIM + (tx << 3);
        float4 oa = make_float4(o_acc[i][0] * inv, o_acc[i][1] * inv,
                                o_acc[i][2] * inv, o_acc[i][3] * inv);
        float4 ob = make_float4(o_acc[i][4] * inv, o_acc[i][5] * inv,
                                o_acc[i][6] * inv, o_acc[i][7] * inv);
        *(float4*)&Obh[row] = oa;
        *(float4*)&Obh[row + 4] = ob;
    }
}

// ---------------------------------------------------------------------------
extern "C" void kernel_launch(void* const* d_in, const int* in_sizes, int n_in,
                              void* d_out, int out_size) {
    (void)in_sizes; (void)n_in; (void)out_size;
    const float* k  = (const float*)d_in[0];
    const float* q  = (const float*)d_in[1];
    const float* v  = (const float*)d_in[2];
    const float* Wk = (const float*)d_in[3];
    const float* Wq = (const float*)d_in[4];
    const float* Wv = (const float*)d_in[5];
    const float* Wu = (const float*)d_in[6];
    float* out = (float*)d_out;

    float *gQ, *gK, *gV, *gO;
    cudaGetSymbolAddress((void**)&gQ, g_Qp);
    cudaGetSymbolAddress((void**)&gK, g_Kp);
    cudaGetSymbolAddress((void**)&gV, g_Vp);
    cudaGetSymbolAddress((void**)&gO, g_Op);

    // Opt-in >48KB dynamic smem (persistent per-function; ignore error if
    // called again during capture).
    cudaFuncSetAttribute(flash_attn, cudaFuncAttributeMaxDynamicSharedMemorySize,
                         SM_BYTES);

    dim3 blk(256);
    // Projections: [8192,128] @ [128,1024] -> [8192,1024]
    dim3 gproj(HEDIM / 64, BT / 64);
    gemm_k<<<gproj, blk>>>(q, Wq, gQ, BT, HEDIM, EDIM);
    gemm_k<<<gproj, blk>>>(k, Wk, gK, BT, HEDIM, EDIM);
    gemm_k<<<gproj, blk>>>(v, Wv, gV, BT, HEDIM, EDIM);

    // Attention
    dim3 gatt(TS / BM, NH, NB);
    flash_attn<<<gatt, blk, SM_BYTES>>>(gQ, gK, gV, gO);

    // Output projection: [8192,1024] @ [1024,128] -> [8192,128]
    dim3 gout(EDIM / 64, BT / 64);
    gemm_k<<<gout, blk>>>(gO, Wu, out, BT, EDIM, HEDIM);
}

// round 2
// speedup vs baseline: 2.4929x; 2.4929x over previous
#include <cuda_runtime.h>
#include <math.h>

#define EDIM 128
#define NH 8
#define NB 2
#define TS 4096
#define HEDIM 1024   // NH*EDIM
#define BT 8192      // NB*TS

// Scratch (device globals; no runtime allocation)
__device__ float g_Qp[(size_t)BT * HEDIM];
__device__ float g_Kp[(size_t)BT * HEDIM];
__device__ float g_Vp[(size_t)BT * HEDIM];
__device__ float g_Op[(size_t)BT * HEDIM];

// ---------------------------------------------------------------------------
// Generic tiled fp32 GEMM (unchanged baseline): C[M,N] = A[M,K] @ B[K,N].
// ---------------------------------------------------------------------------
__global__ __launch_bounds__(256) void gemm_k(const float* __restrict__ A,
                                              const float* __restrict__ B,
                                              float* __restrict__ C,
                                              int M, int N, int K) {
    __shared__ float sA[64][33];
    __shared__ float sB[32][64];
    const int tid = threadIdx.x;
    const int tx = tid & 15, ty = tid >> 4;
    const int n0 = blockIdx.x << 6, m0 = blockIdx.y << 6;
    float acc[4][4] = {};

    for (int k0 = 0; k0 < K; k0 += 32) {
#pragma unroll
        for (int i = 0; i < 8; ++i) {
            int idx = tid + (i << 8);
            int r = idx >> 5, c = idx & 31;
            sA[r][c] = A[(size_t)(m0 + r) * K + (k0 + c)];
        }
#pragma unroll
        for (int i = 0; i < 8; ++i) {
            int idx = tid + (i << 8);
            int r = idx >> 6, c = idx & 63;
            sB[r][c] = B[(size_t)(k0 + r) * N + (n0 + c)];
        }
        __syncthreads();
#pragma unroll
        for (int kk = 0; kk < 32; ++kk) {
            float a0 = sA[(ty << 2) + 0][kk];
            float a1 = sA[(ty << 2) + 1][kk];
            float a2 = sA[(ty << 2) + 2][kk];
            float a3 = sA[(ty << 2) + 3][kk];
            float4 b4 = *(const float4*)&sB[kk][tx << 2];
            acc[0][0] += a0 * b4.x; acc[0][1] += a0 * b4.y;
            acc[0][2] += a0 * b4.z; acc[0][3] += a0 * b4.w;
            acc[1][0] += a1 * b4.x; acc[1][1] += a1 * b4.y;
            acc[1][2] += a1 * b4.z; acc[1][3] += a1 * b4.w;
            acc[2][0] += a2 * b4.x; acc[2][1] += a2 * b4.y;
            acc[2][2] += a2 * b4.z; acc[2][3] += a2 * b4.w;
            acc[3][0] += a3 * b4.x; acc[3][1] += a3 * b4.y;
            acc[3][2] += a3 * b4.z; acc[3][3] += a3 * b4.w;
        }
        __syncthreads();
    }
#pragma unroll
    for (int i = 0; i < 4; ++i)
#pragma unroll
        for (int j = 0; j < 4; ++j)
            C[(size_t)(m0 + (ty << 2) + i) * N + n0 + (tx << 2) + j] = acc[i][j];
}

// ---------------------------------------------------------------------------
// Flash attention on TF32 tensor cores (mma.sync.m16n8k8).
// CTA = 64 queries x one (b,h). 8 warps = 4 M-strips x 2 N-halves.
// 3xTF32 (hi+lo) for QK^T, 1xTF32 for PV.
// ---------------------------------------------------------------------------
#define BM 64
#define BN 64
#define QSTR 132   // [m][k] strides: 132 % 32 == 4 -> conflict-free A-frag gather
#define KSTR 132   // [n][k]: 132 % 32 == 4 -> conflict-free B-frag gather
#define VSTR 136   // [k'][n]: 136 % 32 == 8 -> conflict-free B-frag gather
#define PSTR 68    // [m][k']: 68 % 32 == 4

#define OFF_QHI 0
#define OFF_QLO (OFF_QHI + BM * QSTR)       // 8448
#define OFF_KHI (OFF_QLO + BM * QSTR)       // 16896
#define OFF_KLO (OFF_KHI + BN * KSTR)       // 25344
#define OFF_V   (OFF_KLO + BN * KSTR)       // 33792
#define OFF_P   (OFF_V   + BN * VSTR)       // 42496
#define OFF_RM  (OFF_P   + BM * PSTR)       // 46848
#define OFF_RS  (OFF_RM  + 2 * BM)          // 46976
#define SM_FLOATS (OFF_RS + 2 * BM)         // 47104
#define SM_BYTES (SM_FLOATS * 4)            // 188416
#define OSTR 132                            // O reduce buffer reuses QHI/QLO space

__device__ __forceinline__ float tf32f(float x) {
    unsigned r;
    asm("cvt.rna.tf32.f32 %0, %1;" : "=r"(r) : "f"(x));
    return __uint_as_float(r);
}

#define MMA_TF32(d, a0, a1, a2, a3, b0, b1)                                   \
    asm volatile(                                                             \
        "mma.sync.aligned.m16n8k8.row.col.f32.tf32.tf32.f32 "                 \
        "{%0,%1,%2,%3},{%4,%5,%6,%7},{%8,%9},{%0,%1,%2,%3};"                  \
        : "+f"(d[0]), "+f"(d[1]), "+f"(d[2]), "+f"(d[3])                      \
        : "r"(__float_as_uint(a0)), "r"(__float_as_uint(a1)),                 \
          "r"(__float_as_uint(a2)), "r"(__float_as_uint(a3)),                 \
          "r"(__float_as_uint(b0)), "r"(__float_as_uint(b1)))

__global__ __launch_bounds__(256) void flash_attn_tc(const float* __restrict__ Qg,
                                                     const float* __restrict__ Kg,
                                                     const float* __restrict__ Vg,
                                                     float* __restrict__ Og) {
    extern __shared__ float sm[];
    float* sQhi = sm + OFF_QHI;
    float* sQlo = sm + OFF_QLO;
    float* sKhi = sm + OFF_KHI;
    float* sKlo = sm + OFF_KLO;
    float* sV   = sm + OFF_V;
    float* sP   = sm + OFF_P;
    float* sRM  = sm + OFF_RM;
    float* sRS  = sm + OFF_RS;
    float* sO   = sm;  // reused after main loop

    const int tid = threadIdx.x;
    const int wid = tid >> 5;
    const int lane = tid & 31;
    const int g = lane >> 2;       // group id (row within 8)
    const int tg = lane & 3;       // thread in group
    const int wm = wid >> 1;       // M-strip 0..3 (rows wm*16..wm*16+15)
    const int wn = wid & 1;        // N-half 0..1 (cols wn*32..wn*32+31)

    const int h = blockIdx.y, b = blockIdx.z;
    const int q0 = blockIdx.x * BM;
    const float scale = 0.08838834764831845f;  // 1/sqrt(128)

    const size_t bh_off = (size_t)b * TS * HEDIM + (size_t)h * EDIM;
    const float* Qbh = Qg + bh_off;
    const float* Kbh = Kg + bh_off;
    const float* Vbh = Vg + bh_off;
    float* Obh = Og + bh_off;

    // Load Q tile (pre-scaled) with hi/lo tf32 split: sQ[m][k]
#pragma unroll
    for (int i = 0; i < 8; ++i) {
        int idx = tid + (i << 8);          // 2048 float4s
        int r = idx >> 5, c = (idx & 31) << 2;
        float4 x = *(const float4*)&Qbh[(size_t)(q0 + r) * HEDIM + c];
        x.x *= scale; x.y *= scale; x.z *= scale; x.w *= scale;
        float4 hi = make_float4(tf32f(x.x), tf32f(x.y), tf32f(x.z), tf32f(x.w));
        float4 lo = make_float4(tf32f(x.x - hi.x), tf32f(x.y - hi.y),
                                tf32f(x.z - hi.z), tf32f(x.w - hi.w));
        *(float4*)&sQhi[r * QSTR + c] = hi;
        *(float4*)&sQlo[r * QSTR + c] = lo;
    }

    const int row0 = wm * 16 + g;
    const int row1 = row0 + 8;

    float m0 = -INFINITY, m1 = -INFINITY, l0 = 0.f, l1 = 0.f;
    float o[16][4];
#pragma unroll
    for (int nb = 0; nb < 16; ++nb)
#pragma unroll
        for (int j = 0; j < 4; ++j) o[nb][j] = 0.f;

    for (int kv0 = 0; kv0 < TS; kv0 += BN) {
        // Load K (hi/lo split) and V (tf32) tiles, row-major
#pragma unroll
        for (int i = 0; i < 8; ++i) {
            int idx = tid + (i << 8);
            int r = idx >> 5, c = (idx & 31) << 2;
            float4 x = *(const float4*)&Kbh[(size_t)(kv0 + r) * HEDIM + c];
            float4 hi = make_float4(tf32f(x.x), tf32f(x.y), tf32f(x.z), tf32f(x.w));
            float4 lo = make_float4(tf32f(x.x - hi.x), tf32f(x.y - hi.y),
                                    tf32f(x.z - hi.z), tf32f(x.w - hi.w));
            *(float4*)&sKhi[r * KSTR + c] = hi;
            *(float4*)&sKlo[r * KSTR + c] = lo;
        }
#pragma unroll
        for (int i = 0; i < 8; ++i) {
            int idx = tid + (i << 8);
            int r = idx >> 5, c = (idx & 31) << 2;
            float4 x = *(const float4*)&Vbh[(size_t)(kv0 + r) * HEDIM + c];
            float4 t = make_float4(tf32f(x.x), tf32f(x.y), tf32f(x.z), tf32f(x.w));
            *(float4*)&sV[r * VSTR + c] = t;
        }
        __syncthreads();

        // ---- S = Q @ K^T (3xTF32) ----
        float s[4][4];
#pragma unroll
        for (int nb = 0; nb < 4; ++nb)
#pragma unroll
            for (int j = 0; j < 4; ++j) s[nb][j] = 0.f;

#pragma unroll
        for (int ks = 0; ks < 16; ++ks) {
            const int k0 = ks * 8;
            const int ab = row0 * QSTR + k0 + tg;
            float ah0 = sQhi[ab],            ah1 = sQhi[ab + 8 * QSTR];
            float ah2 = sQhi[ab + 4],        ah3 = sQhi[ab + 8 * QSTR + 4];
            float al0 = sQlo[ab],            al1 = sQlo[ab + 8 * QSTR];
            float al2 = sQlo[ab + 4],        al3 = sQlo[ab + 8 * QSTR + 4];
#pragma unroll
            for (int nb = 0; nb < 4; ++nb) {
                const int bb = (wn * 32 + nb * 8 + g) * KSTR + k0 + tg;
                float bh0 = sKhi[bb], bh1 = sKhi[bb + 4];
                float bl0 = sKlo[bb], bl1 = sKlo[bb + 4];
                MMA_TF32(s[nb], ah0, ah1, ah2, ah3, bh0, bh1);
                MMA_TF32(s[nb], al0, al1, al2, al3, bh0, bh1);
                MMA_TF32(s[nb], ah0, ah1, ah2, ah3, bl0, bl1);
            }
        }

        // ---- online softmax (row stats shared across the wn pair) ----
        float mx0 = -INFINITY, mx1 = -INFINITY;
#pragma unroll
        for (int nb = 0; nb < 4; ++nb) {
            mx0 = fmaxf(mx0, fmaxf(s[nb][0], s[nb][1]));
            mx1 = fmaxf(mx1, fmaxf(s[nb][2], s[nb][3]));
        }
        mx0 = fmaxf(mx0, __shfl_xor_sync(0xffffffffu, mx0, 1));
        mx0 = fmaxf(mx0, __shfl_xor_sync(0xffffffffu, mx0, 2));
        mx1 = fmaxf(mx1, __shfl_xor_sync(0xffffffffu, mx1, 1));
        mx1 = fmaxf(mx1, __shfl_xor_sync(0xffffffffu, mx1, 2));
        if (tg == 0) {
            sRM[wn * BM + row0] = mx0;
            sRM[wn * BM + row1] = mx1;
        }
        __syncthreads();
        mx0 = fmaxf(mx0, sRM[(wn ^ 1) * BM + row0]);
        mx1 = fmaxf(mx1, sRM[(wn ^ 1) * BM + row1]);
        const float mn0 = fmaxf(m0, mx0), mn1 = fmaxf(m1, mx1);
        const float al0f = __expf(m0 - mn0), al1f = __expf(m1 - mn1);
        m0 = mn0; m1 = mn1;

        float ps0 = 0.f, ps1 = 0.f;
#pragma unroll
        for (int nb = 0; nb < 4; ++nb) {
            s[nb][0] = __expf(s[nb][0] - mn0);
            s[nb][1] = __expf(s[nb][1] - mn0);
            s[nb][2] = __expf(s[nb][2] - mn1);
            s[nb][3] = __expf(s[nb][3] - mn1);
            ps0 += s[nb][0] + s[nb][1];
            ps1 += s[nb][2] + s[nb][3];
        }
        ps0 += __shfl_xor_sync(0xffffffffu, ps0, 1);
        ps0 += __shfl_xor_sync(0xffffffffu, ps0, 2);
        ps1 += __shfl_xor_sync(0xffffffffu, ps1, 1);
        ps1 += __shfl_xor_sync(0xffffffffu, ps1, 2);

        // stage P (tf32) to smem: sP[m][k']
#pragma unroll
        for (int nb = 0; nb < 4; ++nb) {
            const int col = wn * 32 + nb * 8 + 2 * tg;
            sP[row0 * PSTR + col]     = tf32f(s[nb][0]);
            sP[row0 * PSTR + col + 1] = tf32f(s[nb][1]);
            sP[row1 * PSTR + col]     = tf32f(s[nb][2]);
            sP[row1 * PSTR + col + 1] = tf32f(s[nb][3]);
        }
        if (tg == 0) {
            sRS[wn * BM + row0] = ps0;
            sRS[wn * BM + row1] = ps1;
        }

        // rescale O accumulators
#pragma unroll
        for (int nb = 0; nb < 16; ++nb) {
            o[nb][0] *= al0f; o[nb][1] *= al0f;
            o[nb][2] *= al1f; o[nb][3] *= al1f;
        }
        __syncthreads();
        l0 = l0 * al0f + ps0 + sRS[(wn ^ 1) * BM + row0];
        l1 = l1 * al1f + ps1 + sRS[(wn ^ 1) * BM + row1];

        // ---- O += P @ V (1xTF32; split-K across the wn pair) ----
#pragma unroll
        for (int ks = 0; ks < 4; ++ks) {
            const int k0 = wn * 32 + ks * 8;
            const int ab = row0 * PSTR + k0 + tg;
            float a0 = sP[ab],     a1 = sP[ab + 8 * PSTR];
            float a2 = sP[ab + 4], a3 = sP[ab + 8 * PSTR + 4];
#pragma unroll
            for (int nb = 0; nb < 16; ++nb) {
                const int bb = (k0 + tg) * VSTR + nb * 8 + g;
                float b0 = sV[bb];
                float b1 = sV[bb + 4 * VSTR];
                MMA_TF32(o[nb], a0, a1, a2, a3, b0, b1);
            }
        }
        __syncthreads();  // protect sK/sV/sP before next tile's loads
    }

    // ---- cross-warp O reduction + write ----
    if (wn == 1) {
#pragma unroll
        for (int nb = 0; nb < 16; ++nb) {
            const int c = nb * 8 + 2 * tg;
            sO[row0 * OSTR + c]     = o[nb][0];
            sO[row0 * OSTR + c + 1] = o[nb][1];
            sO[row1 * OSTR + c]     = o[nb][2];
            sO[row1 * OSTR + c + 1] = o[nb][3];
        }
    }
    __syncthreads();
    if (wn == 0) {
        const float inv0 = 1.f / l0, inv1 = 1.f / l1;
#pragma unroll
        for (int nb = 0; nb < 16; ++nb) {
            const int c = nb * 8 + 2 * tg;
            float2 r0v, r1v;
            r0v.x = (o[nb][0] + sO[row0 * OSTR + c])     * inv0;
            r0v.y = (o[nb][1] + sO[row0 * OSTR + c + 1]) * inv0;
            r1v.x = (o[nb][2] + sO[row1 * OSTR + c])     * inv1;
            r1v.y = (o[nb][3] + sO[row1 * OSTR + c + 1]) * inv1;
            *(float2*)&Obh[(size_t)(q0 + row0) * HEDIM + c] = r0v;
            *(float2*)&Obh[(size_t)(q0 + row1) * HEDIM + c] = r1v;
        }
    }
}

// ---------------------------------------------------------------------------
extern "C" void kernel_launch(void* const* d_in, const int* in_sizes, int n_in,
                              void* d_out, int out_size) {
    (void)in_sizes; (void)n_in; (void)out_size;
    const float* k  = (const float*)d_in[0];
    const float* q  = (const float*)d_in[1];
    const float* v  = (const float*)d_in[2];
    const float* Wk = (const float*)d_in[3];
    const float* Wq = (const float*)d_in[4];
    const float* Wv = (const float*)d_in[5];
    const float* Wu = (const float*)d_in[6];
    float* out = (float*)d_out;

    float *gQ, *gK, *gV, *gO;
    cudaGetSymbolAddress((void**)&gQ, g_Qp);
    cudaGetSymbolAddress((void**)&gK, g_Kp);
    cudaGetSymbolAddress((void**)&gV, g_Vp);
    cudaGetSymbolAddress((void**)&gO, g_Op);

    cudaFuncSetAttribute(flash_attn_tc,
                         cudaFuncAttributeMaxDynamicSharedMemorySize, SM_BYTES);

    dim3 blk(256);
    dim3 gproj(HEDIM / 64, BT / 64);
    gemm_k<<<gproj, blk>>>(q, Wq, gQ, BT, HEDIM, EDIM);
    gemm_k<<<gproj, blk>>>(k, Wk, gK, BT, HEDIM, EDIM);
    gemm_k<<<gproj, blk>>>(v, Wv, gV, BT, HEDIM, EDIM);

    dim3 gatt(TS / BM, NH, NB);
    flash_attn_tc<<<gatt, blk, SM_BYTES>>>(gQ, gK, gV, gO);

    dim3 gout(EDIM / 64, BT / 64);
    gemm_k<<<gout, blk>>>(gO, Wu, out, BT, EDIM, HEDIM);
}

// round 3
// speedup vs baseline: 6.1081x; 2.4502x over previous
#include <cuda_runtime.h>
#include <cuda_fp16.h>
#include <math.h>

#define EDIM 128
#define NH 8
#define NB 2
#define TS 4096
#define HEDIM 1024   // NH*EDIM
#define BT 8192      // NB*TS

// Scratch (device globals; no runtime allocation)
__device__ float g_Qp[(size_t)BT * HEDIM];
__device__ float g_Kp[(size_t)BT * HEDIM];
__device__ float g_Vp[(size_t)BT * HEDIM];
__device__ float g_Op[(size_t)BT * HEDIM];

// ---------------------------------------------------------------------------
// Generic tiled fp32 GEMM (baseline): C[M,N] = A[M,K] @ B[K,N].
// ---------------------------------------------------------------------------
__global__ __launch_bounds__(256) void gemm_k(const float* __restrict__ A,
                                              const float* __restrict__ B,
                                              float* __restrict__ C,
                                              int M, int N, int K) {
    __shared__ float sA[64][33];
    __shared__ float sB[32][64];
    const int tid = threadIdx.x;
    const int tx = tid & 15, ty = tid >> 4;
    const int n0 = blockIdx.x << 6, m0 = blockIdx.y << 6;
    float acc[4][4] = {};

    for (int k0 = 0; k0 < K; k0 += 32) {
#pragma unroll
        for (int i = 0; i < 8; ++i) {
            int idx = tid + (i << 8);
            int r = idx >> 5, c = idx & 31;
            sA[r][c] = A[(size_t)(m0 + r) * K + (k0 + c)];
        }
#pragma unroll
        for (int i = 0; i < 8; ++i) {
            int idx = tid + (i << 8);
            int r = idx >> 6, c = idx & 63;
            sB[r][c] = B[(size_t)(k0 + r) * N + (n0 + c)];
        }
        __syncthreads();
#pragma unroll
        for (int kk = 0; kk < 32; ++kk) {
            float a0 = sA[(ty << 2) + 0][kk];
            float a1 = sA[(ty << 2) + 1][kk];
            float a2 = sA[(ty << 2) + 2][kk];
            float a3 = sA[(ty << 2) + 3][kk];
            float4 b4 = *(const float4*)&sB[kk][tx << 2];
            acc[0][0] += a0 * b4.x; acc[0][1] += a0 * b4.y;
            acc[0][2] += a0 * b4.z; acc[0][3] += a0 * b4.w;
            acc[1][0] += a1 * b4.x; acc[1][1] += a1 * b4.y;
            acc[1][2] += a1 * b4.z; acc[1][3] += a1 * b4.w;
            acc[2][0] += a2 * b4.x; acc[2][1] += a2 * b4.y;
            acc[2][2] += a2 * b4.z; acc[2][3] += a2 * b4.w;
            acc[3][0] += a3 * b4.x; acc[3][1] += a3 * b4.y;
            acc[3][2] += a3 * b4.z; acc[3][3] += a3 * b4.w;
        }
        __syncthreads();
    }
#pragma unroll
    for (int i = 0; i < 4; ++i)
#pragma unroll
        for (int j = 0; j < 4; ++j)
            C[(size_t)(m0 + (ty << 2) + i) * N + n0 + (tx << 2) + j] = acc[i][j];
}

// ---------------------------------------------------------------------------
// Flash attention on FP16 tensor cores (mma.sync.m16n8k16) with ldmatrix.
// CTA = 64 queries x one (b,h). 8 warps = 4 M-strips x 2 N-halves.
// QK^T: 3-product fp16 hi/lo split (fp32-quality). PV: 1-pass fp16.
// ---------------------------------------------------------------------------
#define BM 64
#define BN 64
#define QSTRH 136            // halves per row (272B; 272%128==16 -> ldsm ok)
#define QSTRB 272
#define PSTRH 72             // 144B; 144%128==16
#define PSTRB 144

#define HOFF_QHI 0
#define HOFF_QLO (HOFF_QHI + BM * QSTRH)   // 8704
#define HOFF_KHI (HOFF_QLO + BM * QSTRH)   // 17408
#define HOFF_KLO (HOFF_KHI + BN * QSTRH)   // 26112
#define HOFF_V   (HOFF_KLO + BN * QSTRH)   // 34816
#define HOFF_P   (HOFF_V   + BN * QSTRH)   // 43520
#define HOFF_END (HOFF_P   + BM * PSTRH)   // 48128
#define SM_BYTES (HOFF_END * 2 + 4 * BM * 4)  // 96256 + 1024 = 97280

#define LDSM4(r0, r1, r2, r3, p)                                              \
    asm volatile("ldmatrix.sync.aligned.m8n8.x4.shared.b16 {%0,%1,%2,%3},[%4];" \
                 : "=r"(r0), "=r"(r1), "=r"(r2), "=r"(r3) : "r"(p))
#define LDSM4T(r0, r1, r2, r3, p)                                             \
    asm volatile("ldmatrix.sync.aligned.m8n8.x4.trans.shared.b16 {%0,%1,%2,%3},[%4];" \
                 : "=r"(r0), "=r"(r1), "=r"(r2), "=r"(r3) : "r"(p))

#define MMA16816(d, a0, a1, a2, a3, b0, b1)                                   \
    asm volatile(                                                             \
        "mma.sync.aligned.m16n8k16.row.col.f32.f16.f16.f32 "                  \
        "{%0,%1,%2,%3},{%4,%5,%6,%7},{%8,%9},{%0,%1,%2,%3};"                  \
        : "+f"(d[0]), "+f"(d[1]), "+f"(d[2]), "+f"(d[3])                      \
        : "r"(a0), "r"(a1), "r"(a2), "r"(a3), "r"(b0), "r"(b1))

__device__ __forceinline__ unsigned h2u(__half2 h) {
    return *(unsigned*)&h;
}

__global__ __launch_bounds__(256, 2) void flash_attn_fp16(
    const float* __restrict__ Qg, const float* __restrict__ Kg,
    const float* __restrict__ Vg, float* __restrict__ Og) {
    extern __shared__ __align__(16) char smem[];
    __half* sQhi = (__half*)smem + HOFF_QHI;
    __half* sQlo = (__half*)smem + HOFF_QLO;
    __half* sKhi = (__half*)smem + HOFF_KHI;
    __half* sKlo = (__half*)smem + HOFF_KLO;
    __half* sV   = (__half*)smem + HOFF_V;
    __half* sP   = (__half*)smem + HOFF_P;
    float* sRM = (float*)(smem + HOFF_END * 2);
    float* sRS = sRM + 2 * BM;

    const int tid = threadIdx.x;
    const int wid = tid >> 5;
    const int lane = tid & 31;
    const int g = lane >> 2;    // row-in-8
    const int tg = lane & 3;    // thread-in-group
    const int wm = wid >> 1;    // M-strip (rows wm*16..+15)
    const int wn = wid & 1;     // N-half

    const int h = blockIdx.y, b = blockIdx.z;
    const int q0 = blockIdx.x * BM;
    const float scale = 0.08838834764831845f;  // 1/sqrt(128)

    const size_t bh_off = (size_t)b * TS * HEDIM + (size_t)h * EDIM;
    const float* Qbh = Qg + bh_off;
    const float* Kbh = Kg + bh_off;
    const float* Vbh = Vg + bh_off;
    float* Obh = Og + bh_off;

    const unsigned sbase = (unsigned)__cvta_generic_to_shared(smem);
    // Per-lane ldmatrix base addresses
    const unsigned aQhi0 = sbase + HOFF_QHI * 2 +
        (wm * 16 + (lane & 15)) * QSTRB + (lane >> 4) * 16;
    const unsigned aQlo0 = aQhi0 + BM * QSTRB;  // QLO right after QHI
    const unsigned aKhi0 = sbase + HOFF_KHI * 2 +
        (wn * 32 + (lane & 7) + ((lane >> 4) & 1) * 8) * QSTRB +
        ((lane >> 3) & 1) * 16;
    const unsigned aKlo0 = aKhi0 + BN * QSTRB;
    const unsigned aV0 = sbase + HOFF_V * 2 +
        ((lane & 7) + ((lane >> 3) & 1) * 8) * QSTRB +
        wn * 128 + (lane >> 4) * 16;
    const unsigned aP0 = sbase + HOFF_P * 2 +
        (wm * 16 + (lane & 15)) * PSTRB + (lane >> 4) * 16;

    // ---- Load Q tile (pre-scaled), fp16 hi/lo split ----
#pragma unroll
    for (int i = 0; i < 8; ++i) {
        int idx = tid + (i << 8);
        int r = idx >> 5, c = (idx & 31) << 2;
        float4 x = *(const float4*)&Qbh[(size_t)(q0 + r) * HEDIM + c];
        x.x *= scale; x.y *= scale; x.z *= scale; x.w *= scale;
        __half h0 = __float2half_rn(x.x), h1 = __float2half_rn(x.y);
        __half h2 = __float2half_rn(x.z), h3 = __float2half_rn(x.w);
        __half l0 = __float2half_rn(x.x - __half2float(h0));
        __half l1 = __float2half_rn(x.y - __half2float(h1));
        __half l2 = __float2half_rn(x.z - __half2float(h2));
        __half l3 = __float2half_rn(x.w - __half2float(h3));
        *(__half2*)&sQhi[r * QSTRH + c]     = __halves2half2(h0, h1);
        *(__half2*)&sQhi[r * QSTRH + c + 2] = __halves2half2(h2, h3);
        *(__half2*)&sQlo[r * QSTRH + c]     = __halves2half2(l0, l1);
        *(__half2*)&sQlo[r * QSTRH + c + 2] = __halves2half2(l2, l3);
    }

    const int row0 = wm * 16 + g;
    const int row1 = row0 + 8;

    float m0 = -INFINITY, m1 = -INFINITY, l0s = 0.f, l1s = 0.f;
    float o[8][4];
#pragma unroll
    for (int nb = 0; nb < 8; ++nb)
#pragma unroll
        for (int j = 0; j < 4; ++j) o[nb][j] = 0.f;

    for (int kv0 = 0; kv0 < TS; kv0 += BN) {
        // ---- Load K (hi/lo) and V (fp16) tiles ----
#pragma unroll
        for (int i = 0; i < 8; ++i) {
            int idx = tid + (i << 8);
            int r = idx >> 5, c = (idx & 31) << 2;
            float4 x = *(const float4*)&Kbh[(size_t)(kv0 + r) * HEDIM + c];
            __half h0 = __float2half_rn(x.x), h1 = __float2half_rn(x.y);
            __half h2 = __float2half_rn(x.z), h3 = __float2half_rn(x.w);
            __half l0 = __float2half_rn(x.x - __half2float(h0));
            __half l1 = __float2half_rn(x.y - __half2float(h1));
            __half l2 = __float2half_rn(x.z - __half2float(h2));
            __half l3 = __float2half_rn(x.w - __half2float(h3));
            *(__half2*)&sKhi[r * QSTRH + c]     = __halves2half2(h0, h1);
            *(__half2*)&sKhi[r * QSTRH + c + 2] = __halves2half2(h2, h3);
            *(__half2*)&sKlo[r * QSTRH + c]     = __halves2half2(l0, l1);
            *(__half2*)&sKlo[r * QSTRH + c + 2] = __halves2half2(l2, l3);
            float4 y = *(const float4*)&Vbh[(size_t)(kv0 + r) * HEDIM + c];
            *(__half2*)&sV[r * QSTRH + c]     = __floats2half2_rn(y.x, y.y);
            *(__half2*)&sV[r * QSTRH + c + 2] = __floats2half2_rn(y.z, y.w);
        }
        __syncthreads();

        // ---- S = Q @ K^T : 3-product hi/lo fp16 ----
        float s[4][4];
#pragma unroll
        for (int nb = 0; nb < 4; ++nb)
#pragma unroll
            for (int j = 0; j < 4; ++j) s[nb][j] = 0.f;

        unsigned aQhi = aQhi0, aQlo = aQlo0, aKhi = aKhi0, aKlo = aKlo0;
#pragma unroll
        for (int ks = 0; ks < 8; ++ks) {
            unsigned qh0, qh1, qh2, qh3, ql0, ql1, ql2, ql3;
            unsigned kh0, kh1, kh2, kh3, kh4, kh5, kh6, kh7;
            unsigned kl0, kl1, kl2, kl3, kl4, kl5, kl6, kl7;
            LDSM4(qh0, qh1, qh2, qh3, aQhi);
            LDSM4(ql0, ql1, ql2, ql3, aQlo);
            LDSM4(kh0, kh1, kh2, kh3, aKhi);
            LDSM4(kh4, kh5, kh6, kh7, aKhi + 16 * QSTRB);
            LDSM4(kl0, kl1, kl2, kl3, aKlo);
            LDSM4(kl4, kl5, kl6, kl7, aKlo + 16 * QSTRB);
            MMA16816(s[0], qh0, qh1, qh2, qh3, kh0, kh1);
            MMA16816(s[1], qh0, qh1, qh2, qh3, kh2, kh3);
            MMA16816(s[2], qh0, qh1, qh2, qh3, kh4, kh5);
            MMA16816(s[3], qh0, qh1, qh2, qh3, kh6, kh7);
            MMA16816(s[0], ql0, ql1, ql2, ql3, kh0, kh1);
            MMA16816(s[1], ql0, ql1, ql2, ql3, kh2, kh3);
            MMA16816(s[2], ql0, ql1, ql2, ql3, kh4, kh5);
            MMA16816(s[3], ql0, ql1, ql2, ql3, kh6, kh7);
            MMA16816(s[0], qh0, qh1, qh2, qh3, kl0, kl1);
            MMA16816(s[1], qh0, qh1, qh2, qh3, kl2, kl3);
            MMA16816(s[2], qh0, qh1, qh2, qh3, kl4, kl5);
            MMA16816(s[3], qh0, qh1, qh2, qh3, kl6, kl7);
            aQhi += 32; aQlo += 32; aKhi += 32; aKlo += 32;
        }

        // ---- online softmax (row stats shared across the wn pair) ----
        float mx0 = -INFINITY, mx1 = -INFINITY;
#pragma unroll
        for (int nb = 0; nb < 4; ++nb) {
            mx0 = fmaxf(mx0, fmaxf(s[nb][0], s[nb][1]));
            mx1 = fmaxf(mx1, fmaxf(s[nb][2], s[nb][3]));
        }
        mx0 = fmaxf(mx0, __shfl_xor_sync(0xffffffffu, mx0, 1));
        mx0 = fmaxf(mx0, __shfl_xor_sync(0xffffffffu, mx0, 2));
        mx1 = fmaxf(mx1, __shfl_xor_sync(0xffffffffu, mx1, 1));
        mx1 = fmaxf(mx1, __shfl_xor_sync(0xffffffffu, mx1, 2));
        if (tg == 0) {
            sRM[wn * BM + row0] = mx0;
            sRM[wn * BM + row1] = mx1;
        }
        __syncthreads();
        mx0 = fmaxf(mx0, sRM[(wn ^ 1) * BM + row0]);
        mx1 = fmaxf(mx1, sRM[(wn ^ 1) * BM + row1]);
        const float mn0 = fmaxf(m0, mx0), mn1 = fmaxf(m1, mx1);
        const float al0 = __expf(m0 - mn0), al1 = __expf(m1 - mn1);
        m0 = mn0; m1 = mn1;

        float ps0 = 0.f, ps1 = 0.f;
#pragma unroll
        for (int nb = 0; nb < 4; ++nb) {
            s[nb][0] = __expf(s[nb][0] - mn0);
            s[nb][1] = __expf(s[nb][1] - mn0);
            s[nb][2] = __expf(s[nb][2] - mn1);
            s[nb][3] = __expf(s[nb][3] - mn1);
            ps0 += s[nb][0] + s[nb][1];
            ps1 += s[nb][2] + s[nb][3];
        }
        ps0 += __shfl_xor_sync(0xffffffffu, ps0, 1);
        ps0 += __shfl_xor_sync(0xffffffffu, ps0, 2);
        ps1 += __shfl_xor_sync(0xffffffffu, ps1, 1);
        ps1 += __shfl_xor_sync(0xffffffffu, ps1, 2);

        // stage P (fp16) to smem
#pragma unroll
        for (int nb = 0; nb < 4; ++nb) {
            const int col = wn * 32 + nb * 8 + 2 * tg;
            *(__half2*)&sP[row0 * PSTRH + col] =
                __floats2half2_rn(s[nb][0], s[nb][1]);
            *(__half2*)&sP[row1 * PSTRH + col] =
                __floats2half2_rn(s[nb][2], s[nb][3]);
        }
        if (tg == 0) {
            sRS[wn * BM + row0] = ps0;
            sRS[wn * BM + row1] = ps1;
        }

        // rescale O accumulators
#pragma unroll
        for (int nb = 0; nb < 8; ++nb) {
            o[nb][0] *= al0; o[nb][1] *= al0;
            o[nb][2] *= al1; o[nb][3] *= al1;
        }
        __syncthreads();
        l0s = l0s * al0 + ps0 + sRS[(wn ^ 1) * BM + row0];
        l1s = l1s * al1 + ps1 + sRS[(wn ^ 1) * BM + row1];

        // ---- O += P @ V (1-pass fp16). Warp owns 64 O-cols (wn half). ----
        unsigned aP = aP0, aV = aV0;
#pragma unroll
        for (int ks = 0; ks < 4; ++ks) {
            unsigned p0, p1, p2, p3;
            LDSM4(p0, p1, p2, p3, aP);
            unsigned av = aV;
#pragma unroll
            for (int np = 0; np < 4; ++np) {
                unsigned v0, v1, v2, v3;
                LDSM4T(v0, v1, v2, v3, av);
                MMA16816(o[np * 2 + 0], p0, p1, p2, p3, v0, v1);
                MMA16816(o[np * 2 + 1], p0, p1, p2, p3, v2, v3);
                av += 32;
            }
            aP += 32;
            aV += 16 * QSTRB;
        }
        __syncthreads();  // protect K/V/P (and sRM/sRS) before next tile
    }

    // ---- normalize + write O ----
    const float inv0 = 1.f / l0s, inv1 = 1.f / l1s;
#pragma unroll
    for (int nb = 0; nb < 8; ++nb) {
        const int col = wn * 64 + nb * 8 + 2 * tg;
        float2 r0v = make_float2(o[nb][0] * inv0, o[nb][1] * inv0);
        float2 r1v = make_float2(o[nb][2] * inv1, o[nb][3] * inv1);
        *(float2*)&Obh[(size_t)(q0 + row0) * HEDIM + col] = r0v;
        *(float2*)&Obh[(size_t)(q0 + row1) * HEDIM + col] = r1v;
    }
}

// ---------------------------------------------------------------------------
extern "C" void kernel_launch(void* const* d_in, const int* in_sizes, int n_in,
                              void* d_out, int out_size) {
    (void)in_sizes; (void)n_in; (void)out_size;
    const float* k  = (const float*)d_in[0];
    const float* q  = (const float*)d_in[1];
    const float* v  = (const float*)d_in[2];
    const float* Wk = (const float*)d_in[3];
    const float* Wq = (const float*)d_in[4];
    const float* Wv = (const float*)d_in[5];
    const float* Wu = (const float*)d_in[6];
    float* out = (float*)d_out;

    float *gQ, *gK, *gV, *gO;
    cudaGetSymbolAddress((void**)&gQ, g_Qp);
    cudaGetSymbolAddress((void**)&gK, g_Kp);
    cudaGetSymbolAddress((void**)&gV, g_Vp);
    cudaGetSymbolAddress((void**)&gO, g_Op);

    cudaFuncSetAttribute(flash_attn_fp16,
                         cudaFuncAttributeMaxDynamicSharedMemorySize, SM_BYTES);

    dim3 blk(256);
    dim3 gproj(HEDIM / 64, BT / 64);
    gemm_k<<<gproj, blk>>>(q, Wq, gQ, BT, HEDIM, EDIM);
    gemm_k<<<gproj, blk>>>(k, Wk, gK, BT, HEDIM, EDIM);
    gemm_k<<<gproj, blk>>>(v, Wv, gV, BT, HEDIM, EDIM);

    dim3 gatt(TS / BM, NH, NB);
    flash_attn_fp16<<<gatt, blk, SM_BYTES>>>(gQ, gK, gV, gO);

    dim3 gout(EDIM / 64, BT / 64);
    gemm_k<<<gout, blk>>>(gO, Wu, out, BT, EDIM, HEDIM);
}

// round 4
// speedup vs baseline: 6.4781x; 1.0606x over previous
#include <cuda_runtime.h>
#include <cuda_fp16.h>
#include <math.h>

#define EDIM 128
#define NH 8
#define NB 2
#define TS 4096
#define HEDIM 1024   // NH*EDIM
#define BT 8192      // NB*TS

// Scratch (device globals; no runtime allocation)
__device__ __half g_Qhi[(size_t)BT * HEDIM];
__device__ __half g_Qlo[(size_t)BT * HEDIM];
__device__ __half g_Khi[(size_t)BT * HEDIM];
__device__ __half g_Klo[(size_t)BT * HEDIM];
__device__ __half g_Vh [(size_t)BT * HEDIM];
__device__ float  g_Op [(size_t)BT * HEDIM];

// ---------------------------------------------------------------------------
// fp32 GEMM with fp16 hi/lo epilogue: Chi/Clo[M,N] = toh16split(scale*A@B).
// ---------------------------------------------------------------------------
__global__ __launch_bounds__(256) void gemm_hilo(const float* __restrict__ A,
                                                 const float* __restrict__ B,
                                                 __half* __restrict__ Chi,
                                                 __half* __restrict__ Clo,
                                                 int M, int N, int K,
                                                 float scale) {
    __shared__ float sA[64][33];
    __shared__ float sB[32][64];
    const int tid = threadIdx.x;
    const int tx = tid & 15, ty = tid >> 4;
    const int n0 = blockIdx.x << 6, m0 = blockIdx.y << 6;
    float acc[4][4] = {};

    for (int k0 = 0; k0 < K; k0 += 32) {
#pragma unroll
        for (int i = 0; i < 8; ++i) {
            int idx = tid + (i << 8);
            int r = idx >> 5, c = idx & 31;
            sA[r][c] = A[(size_t)(m0 + r) * K + (k0 + c)];
        }
#pragma unroll
        for (int i = 0; i < 8; ++i) {
            int idx = tid + (i << 8);
            int r = idx >> 6, c = idx & 63;
            sB[r][c] = B[(size_t)(k0 + r) * N + (n0 + c)];
        }
        __syncthreads();
#pragma unroll
        for (int kk = 0; kk < 32; ++kk) {
            float a0 = sA[(ty << 2) + 0][kk];
            float a1 = sA[(ty << 2) + 1][kk];
            float a2 = sA[(ty << 2) + 2][kk];
            float a3 = sA[(ty << 2) + 3][kk];
            float4 b4 = *(const float4*)&sB[kk][tx << 2];
            acc[0][0] += a0 * b4.x; acc[0][1] += a0 * b4.y;
            acc[0][2] += a0 * b4.z; acc[0][3] += a0 * b4.w;
            acc[1][0] += a1 * b4.x; acc[1][1] += a1 * b4.y;
            acc[1][2] += a1 * b4.z; acc[1][3] += a1 * b4.w;
            acc[2][0] += a2 * b4.x; acc[2][1] += a2 * b4.y;
            acc[2][2] += a2 * b4.z; acc[2][3] += a2 * b4.w;
            acc[3][0] += a3 * b4.x; acc[3][1] += a3 * b4.y;
            acc[3][2] += a3 * b4.z; acc[3][3] += a3 * b4.w;
        }
        __syncthreads();
    }
#pragma unroll
    for (int i = 0; i < 4; ++i) {
        size_t base = (size_t)(m0 + (ty << 2) + i) * N + n0 + (tx << 2);
        __half h[4], l[4];
#pragma unroll
        for (int j = 0; j < 4; ++j) {
            float v = acc[i][j] * scale;
            h[j] = __float2half_rn(v);
            l[j] = __float2half_rn(v - __half2float(h[j]));
        }
        *(__half2*)&Chi[base]     = __halves2half2(h[0], h[1]);
        *(__half2*)&Chi[base + 2] = __halves2half2(h[2], h[3]);
        *(__half2*)&Clo[base]     = __halves2half2(l[0], l[1]);
        *(__half2*)&Clo[base + 2] = __halves2half2(l[2], l[3]);
    }
}

// fp32 GEMM with plain fp16 epilogue.
__global__ __launch_bounds__(256) void gemm_h16(const float* __restrict__ A,
                                                const float* __restrict__ B,
                                                __half* __restrict__ C,
                                                int M, int N, int K) {
    __shared__ float sA[64][33];
    __shared__ float sB[32][64];
    const int tid = threadIdx.x;
    const int tx = tid & 15, ty = tid >> 4;
    const int n0 = blockIdx.x << 6, m0 = blockIdx.y << 6;
    float acc[4][4] = {};

    for (int k0 = 0; k0 < K; k0 += 32) {
#pragma unroll
        for (int i = 0; i < 8; ++i) {
            int idx = tid + (i << 8);
            int r = idx >> 5, c = idx & 31;
            sA[r][c] = A[(size_t)(m0 + r) * K + (k0 + c)];
        }
#pragma unroll
        for (int i = 0; i < 8; ++i) {
            int idx = tid + (i << 8);
            int r = idx >> 6, c = idx & 63;
            sB[r][c] = B[(size_t)(k0 + r) * N + (n0 + c)];
        }
        __syncthreads();
#pragma unroll
        for (int kk = 0; kk < 32; ++kk) {
            float a0 = sA[(ty << 2) + 0][kk];
            float a1 = sA[(ty << 2) + 1][kk];
            float a2 = sA[(ty << 2) + 2][kk];
            float a3 = sA[(ty << 2) + 3][kk];
            float4 b4 = *(const float4*)&sB[kk][tx << 2];
            acc[0][0] += a0 * b4.x; acc[0][1] += a0 * b4.y;
            acc[0][2] += a0 * b4.z; acc[0][3] += a0 * b4.w;
            acc[1][0] += a1 * b4.x; acc[1][1] += a1 * b4.y;
            acc[1][2] += a1 * b4.z; acc[1][3] += a1 * b4.w;
            acc[2][0] += a2 * b4.x; acc[2][1] += a2 * b4.y;
            acc[2][2] += a2 * b4.z; acc[2][3] += a2 * b4.w;
            acc[3][0] += a3 * b4.x; acc[3][1] += a3 * b4.y;
            acc[3][2] += a3 * b4.z; acc[3][3] += a3 * b4.w;
        }
        __syncthreads();
    }
#pragma unroll
    for (int i = 0; i < 4; ++i) {
        size_t base = (size_t)(m0 + (ty << 2) + i) * N + n0 + (tx << 2);
        *(__half2*)&C[base] = __floats2half2_rn(acc[i][0], acc[i][1]);
        *(__half2*)&C[base + 2] = __floats2half2_rn(acc[i][2], acc[i][3]);
    }
}

// ---------------------------------------------------------------------------
// fp32 GEMM (final output projection): C[M,N] = A[M,K] @ B[K,N].
// ---------------------------------------------------------------------------
__global__ __launch_bounds__(256) void gemm_k(const float* __restrict__ A,
                                              const float* __restrict__ B,
                                              float* __restrict__ C,
                                              int M, int N, int K) {
    __shared__ float sA[64][33];
    __shared__ float sB[32][64];
    const int tid = threadIdx.x;
    const int tx = tid & 15, ty = tid >> 4;
    const int n0 = blockIdx.x << 6, m0 = blockIdx.y << 6;
    float acc[4][4] = {};

    for (int k0 = 0; k0 < K; k0 += 32) {
#pragma unroll
        for (int i = 0; i < 8; ++i) {
            int idx = tid + (i << 8);
            int r = idx >> 5, c = idx & 31;
            sA[r][c] = A[(size_t)(m0 + r) * K + (k0 + c)];
        }
#pragma unroll
        for (int i = 0; i < 8; ++i) {
            int idx = tid + (i << 8);
            int r = idx >> 6, c = idx & 63;
            sB[r][c] = B[(size_t)(k0 + r) * N + (n0 + c)];
        }
        __syncthreads();
#pragma unroll
        for (int kk = 0; kk < 32; ++kk) {
            float a0 = sA[(ty << 2) + 0][kk];
            float a1 = sA[(ty << 2) + 1][kk];
            float a2 = sA[(ty << 2) + 2][kk];
            float a3 = sA[(ty << 2) + 3][kk];
            float4 b4 = *(const float4*)&sB[kk][tx << 2];
            acc[0][0] += a0 * b4.x; acc[0][1] += a0 * b4.y;
            acc[0][2] += a0 * b4.z; acc[0][3] += a0 * b4.w;
            acc[1][0] += a1 * b4.x; acc[1][1] += a1 * b4.y;
            acc[1][2] += a1 * b4.z; acc[1][3] += a1 * b4.w;
            acc[2][0] += a2 * b4.x; acc[2][1] += a2 * b4.y;
            acc[2][2] += a2 * b4.z; acc[2][3] += a2 * b4.w;
            acc[3][0] += a3 * b4.x; acc[3][1] += a3 * b4.y;
            acc[3][2] += a3 * b4.z; acc[3][3] += a3 * b4.w;
        }
        __syncthreads();
    }
#pragma unroll
    for (int i = 0; i < 4; ++i)
#pragma unroll
        for (int j = 0; j < 4; ++j)
            C[(size_t)(m0 + (ty << 2) + i) * N + n0 + (tx << 2) + j] = acc[i][j];
}

// ---------------------------------------------------------------------------
// Flash attention, fp16 tensor cores, preconverted operands + cp.async.
// ---------------------------------------------------------------------------
#define BM 64
#define BN 64
#define QSTRH 136            // halves per row (272B)
#define QSTRB 272
#define PSTRH 72             // 144B
#define PSTRB 144

#define HOFF_QHI 0
#define HOFF_QLO (HOFF_QHI + BM * QSTRH)   // 8704
#define HOFF_KHI (HOFF_QLO + BM * QSTRH)   // 17408
#define HOFF_KLO (HOFF_KHI + BN * QSTRH)   // 26112
#define HOFF_V   (HOFF_KLO + BN * QSTRH)   // 34816
#define HOFF_P   (HOFF_V   + BN * QSTRH)   // 43520
#define HOFF_END (HOFF_P   + BM * PSTRH)   // 48128
#define SM_BYTES (HOFF_END * 2 + 4 * BM * 4)  // 97280

#define LDSM4(r0, r1, r2, r3, p)                                              \
    asm volatile("ldmatrix.sync.aligned.m8n8.x4.shared.b16 {%0,%1,%2,%3},[%4];" \
                 : "=r"(r0), "=r"(r1), "=r"(r2), "=r"(r3) : "r"(p))
#define LDSM4T(r0, r1, r2, r3, p)                                             \
    asm volatile("ldmatrix.sync.aligned.m8n8.x4.trans.shared.b16 {%0,%1,%2,%3},[%4];" \
                 : "=r"(r0), "=r"(r1), "=r"(r2), "=r"(r3) : "r"(p))

#define MMA16816(d, a0, a1, a2, a3, b0, b1)                                   \
    asm volatile(                                                             \
        "mma.sync.aligned.m16n8k16.row.col.f32.f16.f16.f32 "                  \
        "{%0,%1,%2,%3},{%4,%5,%6,%7},{%8,%9},{%0,%1,%2,%3};"                  \
        : "+f"(d[0]), "+f"(d[1]), "+f"(d[2]), "+f"(d[3])                      \
        : "r"(a0), "r"(a1), "r"(a2), "r"(a3), "r"(b0), "r"(b1))

#define CPA16(dst, src)                                                       \
    asm volatile("cp.async.cg.shared.global [%0], [%1], 16;" ::               \
                 "r"(dst), "l"(src))
#define CP_COMMIT() asm volatile("cp.async.commit_group;")
#define CP_WAIT0()  asm volatile("cp.async.wait_group 0;")

__global__ __launch_bounds__(256, 2) void flash_attn_fp16(
    const __half* __restrict__ Qhi_g, const __half* __restrict__ Qlo_g,
    const __half* __restrict__ Khi_g, const __half* __restrict__ Klo_g,
    const __half* __restrict__ Vg, float* __restrict__ Og) {
    extern __shared__ __align__(16) char smem[];
    __half* sP = (__half*)smem + HOFF_P;
    float* sRM = (float*)(smem + HOFF_END * 2);
    float* sRS = sRM + 2 * BM;

    const int tid = threadIdx.x;
    const int wid = tid >> 5;
    const int lane = tid & 31;
    const int g = lane >> 2;
    const int tg = lane & 3;
    const int wm = wid >> 1;
    const int wn = wid & 1;

    const int h = blockIdx.y, b = blockIdx.z;
    const int q0 = blockIdx.x * BM;

    const size_t bh_off = (size_t)b * TS * HEDIM + (size_t)h * EDIM;
    const __half* Qhi_bh = Qhi_g + bh_off;
    const __half* Qlo_bh = Qlo_g + bh_off;
    const __half* Khi_bh = Khi_g + bh_off;
    const __half* Klo_bh = Klo_g + bh_off;
    const __half* Vbh = Vg + bh_off;
    float* Obh = Og + bh_off;

    const unsigned sbase = (unsigned)__cvta_generic_to_shared(smem);
    const unsigned aQhi0 = sbase + HOFF_QHI * 2 +
        (wm * 16 + (lane & 15)) * QSTRB + (lane >> 4) * 16;
    const unsigned aQlo0 = aQhi0 + BM * QSTRB;
    const unsigned aKhi0 = sbase + HOFF_KHI * 2 +
        (wn * 32 + (lane & 7) + ((lane >> 4) & 1) * 8) * QSTRB +
        ((lane >> 3) & 1) * 16;
    const unsigned aKlo0 = aKhi0 + BN * QSTRB;
    const unsigned aV0 = sbase + HOFF_V * 2 +
        ((lane & 7) + ((lane >> 3) & 1) * 8) * QSTRB +
        wn * 128 + (lane >> 4) * 16;
    const unsigned aP0 = sbase + HOFF_P * 2 +
        (wm * 16 + (lane & 15)) * PSTRB + (lane >> 4) * 16;

    // ---- prefetch Q tile (hi/lo) via cp.async: 64 rows x 16 chunks each ----
    {
        const unsigned dQhi = sbase + HOFF_QHI * 2;
        const unsigned dQlo = sbase + HOFF_QLO * 2;
#pragma unroll
        for (int i = 0; i < 4; ++i) {
            int idx = tid + (i << 8);          // 0..1023
            int r = idx >> 4, c = idx & 15;
            const size_t goff = (size_t)(q0 + r) * HEDIM + c * 8;
            CPA16(dQhi + r * QSTRB + c * 16, Qhi_bh + goff);
            CPA16(dQlo + r * QSTRB + c * 16, Qlo_bh + goff);
        }
    }

    const int row0 = wm * 16 + g;
    const int row1 = row0 + 8;

    float m0 = -INFINITY, m1 = -INFINITY, l0s = 0.f, l1s = 0.f;
    float o[8][4];
#pragma unroll
    for (int nb = 0; nb < 8; ++nb)
#pragma unroll
        for (int j = 0; j < 4; ++j) o[nb][j] = 0.f;

    const unsigned dKhi = sbase + HOFF_KHI * 2;
    const unsigned dKlo = sbase + HOFF_KLO * 2;
    const unsigned dV   = sbase + HOFF_V * 2;

    for (int kv0 = 0; kv0 < TS; kv0 += BN) {
        // ---- async-load Khi/Klo/V tiles ----
#pragma unroll
        for (int i = 0; i < 4; ++i) {
            int idx = tid + (i << 8);
            int r = idx >> 4, c = idx & 15;
            const size_t goff = (size_t)(kv0 + r) * HEDIM + c * 8;
            const unsigned soff = r * QSTRB + c * 16;
            CPA16(dKhi + soff, Khi_bh + goff);
            CPA16(dKlo + soff, Klo_bh + goff);
            CPA16(dV + soff, Vbh + goff);
        }
        CP_COMMIT();
        CP_WAIT0();
        __syncthreads();

        // ---- S = Q @ K^T : 3-product hi/lo fp16 ----
        float s[4][4];
#pragma unroll
        for (int nb = 0; nb < 4; ++nb)
#pragma unroll
            for (int j = 0; j < 4; ++j) s[nb][j] = 0.f;

        unsigned aQhi = aQhi0, aQlo = aQlo0, aKhi = aKhi0, aKlo = aKlo0;
#pragma unroll
        for (int ks = 0; ks < 8; ++ks) {
            unsigned qh0, qh1, qh2, qh3, ql0, ql1, ql2, ql3;
            unsigned kh0, kh1, kh2, kh3, kh4, kh5, kh6, kh7;
            unsigned kl0, kl1, kl2, kl3, kl4, kl5, kl6, kl7;
            LDSM4(qh0, qh1, qh2, qh3, aQhi);
            LDSM4(ql0, ql1, ql2, ql3, aQlo);
            LDSM4(kh0, kh1, kh2, kh3, aKhi);
            LDSM4(kh4, kh5, kh6, kh7, aKhi + 16 * QSTRB);
            LDSM4(kl0, kl1, kl2, kl3, aKlo);
            LDSM4(kl4, kl5, kl6, kl7, aKlo + 16 * QSTRB);
            MMA16816(s[0], qh0, qh1, qh2, qh3, kh0, kh1);
            MMA16816(s[1], qh0, qh1, qh2, qh3, kh2, kh3);
            MMA16816(s[2], qh0, qh1, qh2, qh3, kh4, kh5);
            MMA16816(s[3], qh0, qh1, qh2, qh3, kh6, kh7);
            MMA16816(s[0], ql0, ql1, ql2, ql3, kh0, kh1);
            MMA16816(s[1], ql0, ql1, ql2, ql3, kh2, kh3);
            MMA16816(s[2], ql0, ql1, ql2, ql3, kh4, kh5);
            MMA16816(s[3], ql0, ql1, ql2, ql3, kh6, kh7);
            MMA16816(s[0], qh0, qh1, qh2, qh3, kl0, kl1);
            MMA16816(s[1], qh0, qh1, qh2, qh3, kl2, kl3);
            MMA16816(s[2], qh0, qh1, qh2, qh3, kl4, kl5);
            MMA16816(s[3], qh0, qh1, qh2, qh3, kl6, kl7);
            aQhi += 32; aQlo += 32; aKhi += 32; aKlo += 32;
        }

        // ---- online softmax (row stats shared across the wn pair) ----
        float mx0 = -INFINITY, mx1 = -INFINITY;
#pragma unroll
        for (int nb = 0; nb < 4; ++nb) {
            mx0 = fmaxf(mx0, fmaxf(s[nb][0], s[nb][1]));
            mx1 = fmaxf(mx1, fmaxf(s[nb][2], s[nb][3]));
        }
        mx0 = fmaxf(mx0, __shfl_xor_sync(0xffffffffu, mx0, 1));
        mx0 = fmaxf(mx0, __shfl_xor_sync(0xffffffffu, mx0, 2));
        mx1 = fmaxf(mx1, __shfl_xor_sync(0xffffffffu, mx1, 1));
        mx1 = fmaxf(mx1, __shfl_xor_sync(0xffffffffu, mx1, 2));
        if (tg == 0) {
            sRM[wn * BM + row0] = mx0;
            sRM[wn * BM + row1] = mx1;
        }
        __syncthreads();
        mx0 = fmaxf(mx0, sRM[(wn ^ 1) * BM + row0]);
        mx1 = fmaxf(mx1, sRM[(wn ^ 1) * BM + row1]);
        const float mn0 = fmaxf(m0, mx0), mn1 = fmaxf(m1, mx1);
        const float al0 = __expf(m0 - mn0), al1 = __expf(m1 - mn1);
        m0 = mn0; m1 = mn1;

        float ps0 = 0.f, ps1 = 0.f;
#pragma unroll
        for (int nb = 0; nb < 4; ++nb) {
            s[nb][0] = __expf(s[nb][0] - mn0);
            s[nb][1] = __expf(s[nb][1] - mn0);
            s[nb][2] = __expf(s[nb][2] - mn1);
            s[nb][3] = __expf(s[nb][3] - mn1);
            ps0 += s[nb][0] + s[nb][1];
            ps1 += s[nb][2] + s[nb][3];
        }
        ps0 += __shfl_xor_sync(0xffffffffu, ps0, 1);
        ps0 += __shfl_xor_sync(0xffffffffu, ps0, 2);
        ps1 += __shfl_xor_sync(0xffffffffu, ps1, 1);
        ps1 += __shfl_xor_sync(0xffffffffu, ps1, 2);

        // stage P (fp16) to smem
#pragma unroll
        for (int nb = 0; nb < 4; ++nb) {
            const int col = wn * 32 + nb * 8 + 2 * tg;
            *(__half2*)&sP[row0 * PSTRH + col] =
                __floats2half2_rn(s[nb][0], s[nb][1]);
            *(__half2*)&sP[row1 * PSTRH + col] =
                __floats2half2_rn(s[nb][2], s[nb][3]);
        }
        if (tg == 0) {
            sRS[wn * BM + row0] = ps0;
            sRS[wn * BM + row1] = ps1;
        }

        // rescale O accumulators
#pragma unroll
        for (int nb = 0; nb < 8; ++nb) {
            o[nb][0] *= al0; o[nb][1] *= al0;
            o[nb][2] *= al1; o[nb][3] *= al1;
        }
        __syncthreads();
        l0s = l0s * al0 + ps0 + sRS[(wn ^ 1) * BM + row0];
        l1s = l1s * al1 + ps1 + sRS[(wn ^ 1) * BM + row1];

        // ---- O += P @ V. Warp owns 64 O-cols (wn half). ----
        unsigned aP = aP0, aV = aV0;
#pragma unroll
        for (int ks = 0; ks < 4; ++ks) {
            unsigned p0, p1, p2, p3;
            LDSM4(p0, p1, p2, p3, aP);
            unsigned av = aV;
#pragma unroll
            for (int np = 0; np < 4; ++np) {
                unsigned v0, v1, v2, v3;
                LDSM4T(v0, v1, v2, v3, av);
                MMA16816(o[np * 2 + 0], p0, p1, p2, p3, v0, v1);
                MMA16816(o[np * 2 + 1], p0, p1, p2, p3, v2, v3);
                av += 32;
            }
            aP += 32;
            aV += 16 * QSTRB;
        }
        __syncthreads();  // protect K/V/P (and sRM/sRS) before next tile
    }

    // ---- normalize + write O ----
    const float inv0 = 1.f / l0s, inv1 = 1.f / l1s;
#pragma unroll
    for (int nb = 0; nb < 8; ++nb) {
        const int col = wn * 64 + nb * 8 + 2 * tg;
        float2 r0v = make_float2(o[nb][0] * inv0, o[nb][1] * inv0);
        float2 r1v = make_float2(o[nb][2] * inv1, o[nb][3] * inv1);
        *(float2*)&Obh[(size_t)(q0 + row0) * HEDIM + col] = r0v;
        *(float2*)&Obh[(size_t)(q0 + row1) * HEDIM + col] = r1v;
    }
}

// ---------------------------------------------------------------------------
extern "C" void kernel_launch(void* const* d_in, const int* in_sizes, int n_in,
                              void* d_out, int out_size) {
    (void)in_sizes; (void)n_in; (void)out_size;
    const float* k  = (const float*)d_in[0];
    const float* q  = (const float*)d_in[1];
    const float* v  = (const float*)d_in[2];
    const float* Wk = (const float*)d_in[3];
    const float* Wq = (const float*)d_in[4];
    const float* Wv = (const float*)d_in[5];
    const float* Wu = (const float*)d_in[6];
    float* out = (float*)d_out;

    __half *gQhi, *gQlo, *gKhi, *gKlo, *gVh;
    float* gO;
    cudaGetSymbolAddress((void**)&gQhi, g_Qhi);
    cudaGetSymbolAddress((void**)&gQlo, g_Qlo);
    cudaGetSymbolAddress((void**)&gKhi, g_Khi);
    cudaGetSymbolAddress((void**)&gKlo, g_Klo);
    cudaGetSymbolAddress((void**)&gVh, g_Vh);
    cudaGetSymbolAddress((void**)&gO, g_Op);

    cudaFuncSetAttribute(flash_attn_fp16,
                         cudaFuncAttributeMaxDynamicSharedMemorySize, SM_BYTES);

    const float qscale = 0.08838834764831845f;  // 1/sqrt(128)
    dim3 blk(256);
    dim3 gproj(HEDIM / 64, BT / 64);
    gemm_hilo<<<gproj, blk>>>(q, Wq, gQhi, gQlo, BT, HEDIM, EDIM, qscale);
    gemm_hilo<<<gproj, blk>>>(k, Wk, gKhi, gKlo, BT, HEDIM, EDIM, 1.0f);
    gemm_h16<<<gproj, blk>>>(v, Wv, gVh, BT, HEDIM, EDIM);

    dim3 gatt(TS / BM, NH, NB);
    flash_attn_fp16<<<gatt, blk, SM_BYTES>>>(gQhi, gQlo, gKhi, gKlo, gVh, gO);

    dim3 gout(EDIM / 64, BT / 64);
    gemm_k<<<gout, blk>>>(gO, Wu, out, BT, EDIM, HEDIM);
}

// round 6
// speedup vs baseline: 9.4781x; 1.4631x over previous
#include <cuda_runtime.h>
#include <cuda_fp16.h>
#include <math.h>

#define EDIM 128
#define NH 8
#define NB 2
#define TS 4096
#define HEDIM 1024   // NH*EDIM
#define BT 8192      // NB*TS

// Scratch (device globals; no runtime allocation)
__device__ __half g_Qh[(size_t)BT * HEDIM];
__device__ __half g_Kh[(size_t)BT * HEDIM];
__device__ __half g_Vh[(size_t)BT * HEDIM];
__device__ float  g_Op[(size_t)BT * HEDIM];

// ---------------------------------------------------------------------------
// fp32 GEMM, fp16 epilogue with scale: C = h16(scale * A@B).
// ---------------------------------------------------------------------------
__global__ __launch_bounds__(256) void gemm_h16s(const float* __restrict__ A,
                                                 const float* __restrict__ B,
                                                 __half* __restrict__ C,
                                                 int M, int N, int K,
                                                 float scale) {
    __shared__ float sA[64][33];
    __shared__ float sB[32][64];
    const int tid = threadIdx.x;
    const int tx = tid & 15, ty = tid >> 4;
    const int n0 = blockIdx.x << 6, m0 = blockIdx.y << 6;
    float acc[4][4] = {};
    for (int k0 = 0; k0 < K; k0 += 32) {
#pragma unroll
        for (int i = 0; i < 8; ++i) {
            int idx = tid + (i << 8);
            int r = idx >> 5, c = idx & 31;
            sA[r][c] = A[(size_t)(m0 + r) * K + (k0 + c)];
        }
#pragma unroll
        for (int i = 0; i < 8; ++i) {
            int idx = tid + (i << 8);
            int r = idx >> 6, c = idx & 63;
            sB[r][c] = B[(size_t)(k0 + r) * N + (n0 + c)];
        }
        __syncthreads();
#pragma unroll
        for (int kk = 0; kk < 32; ++kk) {
            float a0 = sA[(ty << 2) + 0][kk];
            float a1 = sA[(ty << 2) + 1][kk];
            float a2 = sA[(ty << 2) + 2][kk];
            float a3 = sA[(ty << 2) + 3][kk];
            float4 b4 = *(const float4*)&sB[kk][tx << 2];
            acc[0][0] += a0 * b4.x; acc[0][1] += a0 * b4.y;
            acc[0][2] += a0 * b4.z; acc[0][3] += a0 * b4.w;
            acc[1][0] += a1 * b4.x; acc[1][1] += a1 * b4.y;
            acc[1][2] += a1 * b4.z; acc[1][3] += a1 * b4.w;
            acc[2][0] += a2 * b4.x; acc[2][1] += a2 * b4.y;
            acc[2][2] += a2 * b4.z; acc[2][3] += a2 * b4.w;
            acc[3][0] += a3 * b4.x; acc[3][1] += a3 * b4.y;
            acc[3][2] += a3 * b4.z; acc[3][3] += a3 * b4.w;
        }
        __syncthreads();
    }
#pragma unroll
    for (int i = 0; i < 4; ++i) {
        size_t base = (size_t)(m0 + (ty << 2) + i) * N + n0 + (tx << 2);
        *(__half2*)&C[base] =
            __floats2half2_rn(acc[i][0] * scale, acc[i][1] * scale);
        *(__half2*)&C[base + 2] =
            __floats2half2_rn(acc[i][2] * scale, acc[i][3] * scale);
    }
}

// fp32 GEMM (final output projection).
__global__ __launch_bounds__(256) void gemm_k(const float* __restrict__ A,
                                              const float* __restrict__ B,
                                              float* __restrict__ C,
                                              int M, int N, int K) {
    __shared__ float sA[64][33];
    __shared__ float sB[32][64];
    const int tid = threadIdx.x;
    const int tx = tid & 15, ty = tid >> 4;
    const int n0 = blockIdx.x << 6, m0 = blockIdx.y << 6;
    float acc[4][4] = {};
    for (int k0 = 0; k0 < K; k0 += 32) {
#pragma unroll
        for (int i = 0; i < 8; ++i) {
            int idx = tid + (i << 8);
            int r = idx >> 5, c = idx & 31;
            sA[r][c] = A[(size_t)(m0 + r) * K + (k0 + c)];
        }
#pragma unroll
        for (int i = 0; i < 8; ++i) {
            int idx = tid + (i << 8);
            int r = idx >> 6, c = idx & 63;
            sB[r][c] = B[(size_t)(k0 + r) * N + (n0 + c)];
        }
        __syncthreads();
#pragma unroll
        for (int kk = 0; kk < 32; ++kk) {
            float a0 = sA[(ty << 2) + 0][kk];
            float a1 = sA[(ty << 2) + 1][kk];
            float a2 = sA[(ty << 2) + 2][kk];
            float a3 = sA[(ty << 2) + 3][kk];
            float4 b4 = *(const float4*)&sB[kk][tx << 2];
            acc[0][0] += a0 * b4.x; acc[0][1] += a0 * b4.y;
            acc[0][2] += a0 * b4.z; acc[0][3] += a0 * b4.w;
            acc[1][0] += a1 * b4.x; acc[1][1] += a1 * b4.y;
            acc[1][2] += a1 * b4.z; acc[1][3] += a1 * b4.w;
            acc[2][0] += a2 * b4.x; acc[2][1] += a2 * b4.y;
            acc[2][2] += a2 * b4.z; acc[2][3] += a2 * b4.w;
            acc[3][0] += a3 * b4.x; acc[3][1] += a3 * b4.y;
            acc[3][2] += a3 * b4.z; acc[3][3] += a3 * b4.w;
        }
        __syncthreads();
    }
#pragma unroll
    for (int i = 0; i < 4; ++i)
#pragma unroll
        for (int j = 0; j < 4; ++j)
            C[(size_t)(m0 + (ty << 2) + i) * N + n0 + (tx << 2) + j] = acc[i][j];
}

// ---------------------------------------------------------------------------
// Flash attention, single-product fp16 mma, Q in regs, KV double-buffered.
// CTA = 64 queries x one (b,h). 8 warps = 4 M-strips x 2 N-halves.
// ---------------------------------------------------------------------------
#define BM 64
#define BN 64
#define NT (TS / BN)
#define QSTRH 136            // halves per row (272B; 272%128==16 -> ldsm ok)
#define QSTRB 272
#define PSTRH 72             // 144B
#define PSTRB 144

#define HOFF_Q  0
#define HOFF_K0 (HOFF_Q  + BM * QSTRH)   // 8704
#define HOFF_V0 (HOFF_K0 + BN * QSTRH)   // 17408
#define HOFF_K1 (HOFF_V0 + BN * QSTRH)   // 26112
#define HOFF_V1 (HOFF_K1 + BN * QSTRH)   // 34816
#define HOFF_P  (HOFF_V1 + BN * QSTRH)   // 43520
#define HOFF_END (HOFF_P + BM * PSTRH)   // 48128
#define SM_BYTES (HOFF_END * 2 + 4 * BM * 4)  // 97280

#define LDSM4(r0, r1, r2, r3, p)                                              \
    asm volatile("ldmatrix.sync.aligned.m8n8.x4.shared.b16 {%0,%1,%2,%3},[%4];" \
                 : "=r"(r0), "=r"(r1), "=r"(r2), "=r"(r3) : "r"(p))
#define LDSM4T(r0, r1, r2, r3, p)                                             \
    asm volatile("ldmatrix.sync.aligned.m8n8.x4.trans.shared.b16 {%0,%1,%2,%3},[%4];" \
                 : "=r"(r0), "=r"(r1), "=r"(r2), "=r"(r3) : "r"(p))

#define MMA16816(d, a0, a1, a2, a3, b0, b1)                                   \
    asm volatile(                                                             \
        "mma.sync.aligned.m16n8k16.row.col.f32.f16.f16.f32 "                  \
        "{%0,%1,%2,%3},{%4,%5,%6,%7},{%8,%9},{%0,%1,%2,%3};"                  \
        : "+f"(d[0]), "+f"(d[1]), "+f"(d[2]), "+f"(d[3])                      \
        : "r"(a0), "r"(a1), "r"(a2), "r"(a3), "r"(b0), "r"(b1))

#define CPA16(dst, src)                                                       \
    asm volatile("cp.async.cg.shared.global [%0], [%1], 16;" ::               \
                 "r"(dst), "l"(src))
#define CP_COMMIT() asm volatile("cp.async.commit_group;")
#define CP_WAIT1()  asm volatile("cp.async.wait_group 1;")
#define CP_WAIT0()  asm volatile("cp.async.wait_group 0;")

__global__ __launch_bounds__(256, 2) void flash_attn_fp16(
    const __half* __restrict__ Qg, const __half* __restrict__ Kg,
    const __half* __restrict__ Vg, float* __restrict__ Og) {
    extern __shared__ __align__(16) char smem[];
    __half* sP = (__half*)smem + HOFF_P;
    float* sRM = (float*)(smem + HOFF_END * 2);
    float* sRS = sRM + 2 * BM;

    const int tid = threadIdx.x;
    const int wid = tid >> 5;
    const int lane = tid & 31;
    const int g = lane >> 2;
    const int tg = lane & 3;
    const int wm = wid >> 1;
    const int wn = wid & 1;

    const int h = blockIdx.y, b = blockIdx.z;
    const int q0 = blockIdx.x * BM;

    const size_t bh_off = (size_t)b * TS * HEDIM + (size_t)h * EDIM;
    const __half* Qbh = Qg + bh_off;
    const __half* Kbh = Kg + bh_off;
    const __half* Vbh = Vg + bh_off;
    float* Obh = Og + bh_off;

    const unsigned sbase = (unsigned)__cvta_generic_to_shared(smem);
    const unsigned aQ0 = sbase + HOFF_Q * 2 +
        (wm * 16 + (lane & 15)) * QSTRB + (lane >> 4) * 16;
    const unsigned aK[2] = {
        sbase + HOFF_K0 * 2 +
            (wn * 32 + (lane & 7) + ((lane >> 4) & 1) * 8) * QSTRB +
            ((lane >> 3) & 1) * 16,
        sbase + HOFF_K1 * 2 +
            (wn * 32 + (lane & 7) + ((lane >> 4) & 1) * 8) * QSTRB +
            ((lane >> 3) & 1) * 16};
    const unsigned aV[2] = {
        sbase + HOFF_V0 * 2 +
            ((lane & 7) + ((lane >> 3) & 1) * 8) * QSTRB +
            wn * 128 + (lane >> 4) * 16,
        sbase + HOFF_V1 * 2 +
            ((lane & 7) + ((lane >> 3) & 1) * 8) * QSTRB +
            wn * 128 + (lane >> 4) * 16};
    const unsigned aP0 = sbase + HOFF_P * 2 +
        (wm * 16 + (lane & 15)) * PSTRB + (lane >> 4) * 16;

    // ---- group 0: Q tile + KV tile 0 ----
    {
        const unsigned dQ = sbase + HOFF_Q * 2;
        const unsigned dK = sbase + HOFF_K0 * 2;
        const unsigned dV = sbase + HOFF_V0 * 2;
#pragma unroll
        for (int i = 0; i < 4; ++i) {
            int idx = tid + (i << 8);          // 0..1023
            int r = idx >> 4, c = idx & 15;
            const size_t goff = (size_t)r * HEDIM + c * 8;
            const unsigned soff = r * QSTRB + c * 16;
            CPA16(dQ + soff, Qbh + (size_t)q0 * HEDIM + goff);
            CPA16(dK + soff, Kbh + goff);
            CPA16(dV + soff, Vbh + goff);
        }
        CP_COMMIT();
    }

    const int row0 = wm * 16 + g;
    const int row1 = row0 + 8;

    float m0 = -INFINITY, m1 = -INFINITY, l0s = 0.f, l1s = 0.f;
    float o[8][4];
#pragma unroll
    for (int nb = 0; nb < 8; ++nb)
#pragma unroll
        for (int j = 0; j < 4; ++j) o[nb][j] = 0.f;

    unsigned qf[8][4];  // persistent Q fragments (k=0..127)

    for (int n = 0; n < NT; ++n) {
        const int buf = n & 1;
        // ---- prefetch KV tile n+1 into the other buffer ----
        if (n + 1 < NT) {
            const unsigned dK = sbase + (buf ? HOFF_K0 : HOFF_K1) * 2;
            const unsigned dV = sbase + (buf ? HOFF_V0 : HOFF_V1) * 2;
            const size_t kvg = (size_t)(n + 1) * BN * HEDIM;
#pragma unroll
            for (int i = 0; i < 4; ++i) {
                int idx = tid + (i << 8);
                int r = idx >> 4, c = idx & 15;
                const size_t goff = kvg + (size_t)r * HEDIM + c * 8;
                const unsigned soff = r * QSTRB + c * 16;
                CPA16(dK + soff, Kbh + goff);
                CPA16(dV + soff, Vbh + goff);
            }
            CP_COMMIT();
            CP_WAIT1();   // tile n's group done
        } else {
            CP_WAIT0();
        }
        __syncthreads();

        if (n == 0) {   // preload Q fragments once
#pragma unroll
            for (int ks = 0; ks < 8; ++ks)
                LDSM4(qf[ks][0], qf[ks][1], qf[ks][2], qf[ks][3],
                      aQ0 + ks * 32);
        }

        // ---- S = Q @ K^T (single-product fp16) ----
        float s[4][4];
#pragma unroll
        for (int nb = 0; nb < 4; ++nb)
#pragma unroll
            for (int j = 0; j < 4; ++j) s[nb][j] = 0.f;

        unsigned ak = aK[buf];
#pragma unroll
        for (int ks = 0; ks < 8; ++ks) {
            unsigned k0r, k1r, k2r, k3r, k4r, k5r, k6r, k7r;
            LDSM4(k0r, k1r, k2r, k3r, ak);
            LDSM4(k4r, k5r, k6r, k7r, ak + 16 * QSTRB);
            MMA16816(s[0], qf[ks][0], qf[ks][1], qf[ks][2], qf[ks][3], k0r, k1r);
            MMA16816(s[1], qf[ks][0], qf[ks][1], qf[ks][2], qf[ks][3], k2r, k3r);
            MMA16816(s[2], qf[ks][0], qf[ks][1], qf[ks][2], qf[ks][3], k4r, k5r);
            MMA16816(s[3], qf[ks][0], qf[ks][1], qf[ks][2], qf[ks][3], k6r, k7r);
            ak += 32;
        }

        // ---- online softmax (row stats shared across wn pair) ----
        float mx0 = -INFINITY, mx1 = -INFINITY;
#pragma unroll
        for (int nb = 0; nb < 4; ++nb) {
            mx0 = fmaxf(mx0, fmaxf(s[nb][0], s[nb][1]));
            mx1 = fmaxf(mx1, fmaxf(s[nb][2], s[nb][3]));
        }
        mx0 = fmaxf(mx0, __shfl_xor_sync(0xffffffffu, mx0, 1));
        mx0 = fmaxf(mx0, __shfl_xor_sync(0xffffffffu, mx0, 2));
        mx1 = fmaxf(mx1, __shfl_xor_sync(0xffffffffu, mx1, 1));
        mx1 = fmaxf(mx1, __shfl_xor_sync(0xffffffffu, mx1, 2));
        if (tg == 0) {
            sRM[wn * BM + row0] = mx0;
            sRM[wn * BM + row1] = mx1;
        }
        __syncthreads();
        mx0 = fmaxf(mx0, sRM[(wn ^ 1) * BM + row0]);
        mx1 = fmaxf(mx1, sRM[(wn ^ 1) * BM + row1]);
        const float mn0 = fmaxf(m0, mx0), mn1 = fmaxf(m1, mx1);
        const float al0 = __expf(m0 - mn0), al1 = __expf(m1 - mn1);
        m0 = mn0; m1 = mn1;

        float ps0 = 0.f, ps1 = 0.f;
#pragma unroll
        for (int nb = 0; nb < 4; ++nb) {
            s[nb][0] = __expf(s[nb][0] - mn0);
            s[nb][1] = __expf(s[nb][1] - mn0);
            s[nb][2] = __expf(s[nb][2] - mn1);
            s[nb][3] = __expf(s[nb][3] - mn1);
            ps0 += s[nb][0] + s[nb][1];
            ps1 += s[nb][2] + s[nb][3];
        }
        ps0 += __shfl_xor_sync(0xffffffffu, ps0, 1);
        ps0 += __shfl_xor_sync(0xffffffffu, ps0, 2);
        ps1 += __shfl_xor_sync(0xffffffffu, ps1, 1);
        ps1 += __shfl_xor_sync(0xffffffffu, ps1, 2);

        // stage P (fp16) to smem
#pragma unroll
        for (int nb = 0; nb < 4; ++nb) {
            const int col = wn * 32 + nb * 8 + 2 * tg;
            *(__half2*)&sP[row0 * PSTRH + col] =
                __floats2half2_rn(s[nb][0], s[nb][1]);
            *(__half2*)&sP[row1 * PSTRH + col] =
                __floats2half2_rn(s[nb][2], s[nb][3]);
        }
        if (tg == 0) {
            sRS[wn * BM + row0] = ps0;
            sRS[wn * BM + row1] = ps1;
        }

        // rescale O accumulators
#pragma unroll
        for (int nb = 0; nb < 8; ++nb) {
            o[nb][0] *= al0; o[nb][1] *= al0;
            o[nb][2] *= al1; o[nb][3] *= al1;
        }
        __syncthreads();
        l0s = l0s * al0 + ps0 + sRS[(wn ^ 1) * BM + row0];
        l1s = l1s * al1 + ps1 + sRS[(wn ^ 1) * BM + row1];

        // ---- O += P @ V. Warp owns 64 O-cols (wn half). ----
        unsigned aP = aP0, av0 = aV[buf];
#pragma unroll
        for (int ks = 0; ks < 4; ++ks) {
            unsigned p0, p1, p2, p3;
            LDSM4(p0, p1, p2, p3, aP);
            unsigned av = av0;
#pragma unroll
            for (int np = 0; np < 4; ++np) {
                unsigned v0, v1, v2, v3;
                LDSM4T(v0, v1, v2, v3, av);
                MMA16816(o[np * 2 + 0], p0, p1, p2, p3, v0, v1);
                MMA16816(o[np * 2 + 1], p0, p1, p2, p3, v2, v3);
                av += 32;
            }
            aP += 32;
            av0 += 16 * QSTRB;
        }
        __syncthreads();  // protect P/sRM/sRS (and this buf) before next tile
    }

    // ---- normalize + write O ----
    const float inv0 = 1.f / l0s, inv1 = 1.f / l1s;
#pragma unroll
    for (int nb = 0; nb < 8; ++nb) {
        const int col = wn * 64 + nb * 8 + 2 * tg;
        float2 r0v = make_float2(o[nb][0] * inv0, o[nb][1] * inv0);
        float2 r1v = make_float2(o[nb][2] * inv1, o[nb][3] * inv1);
        *(float2*)&Obh[(size_t)(q0 + row0) * HEDIM + col] = r0v;
        *(float2*)&Obh[(size_t)(q0 + row1) * HEDIM + col] = r1v;
    }
}

// ---------------------------------------------------------------------------
extern "C" void kernel_launch(void* const* d_in, const int* in_sizes, int n_in,
                              void* d_out, int out_size) {
    (void)in_sizes; (void)n_in; (void)out_size;
    const float* k  = (const float*)d_in[0];
    const float* q  = (const float*)d_in[1];
    const float* v  = (const float*)d_in[2];
    const float* Wk = (const float*)d_in[3];
    const float* Wq = (const float*)d_in[4];
    const float* Wv = (const float*)d_in[5];
    const float* Wu = (const float*)d_in[6];
    float* out = (float*)d_out;

    __half *gQ, *gK, *gV;
    float* gO;
    cudaGetSymbolAddress((void**)&gQ, g_Qh);
    cudaGetSymbolAddress((void**)&gK, g_Kh);
    cudaGetSymbolAddress((void**)&gV, g_Vh);
    cudaGetSymbolAddress((void**)&gO, g_Op);

    cudaFuncSetAttribute(flash_attn_fp16,
                         cudaFuncAttributeMaxDynamicSharedMemorySize, SM_BYTES);

    const float qscale = 0.08838834764831845f;  // 1/sqrt(128)
    dim3 blk(256);
    dim3 gproj(HEDIM / 64, BT / 64);
    gemm_h16s<<<gproj, blk>>>(q, Wq, gQ, BT, HEDIM, EDIM, qscale);
    gemm_h16s<<<gproj, blk>>>(k, Wk, gK, BT, HEDIM, EDIM, 1.0f);
    gemm_h16s<<<gproj, blk>>>(v, Wv, gV, BT, HEDIM, EDIM, 1.0f);

    dim3 gatt(TS / BM, NH, NB);
    flash_attn_fp16<<<gatt, blk, SM_BYTES>>>(gQ, gK, gV, gO);

    dim3 gout(EDIM / 64, BT / 64);
    gemm_k<<<gout, blk>>>(gO, Wu, out, BT, EDIM, HEDIM);
}

// round 8
// speedup vs baseline: 10.6306x; 1.1216x over previous
#include <cuda_runtime.h>
#include <cuda_fp16.h>
#include <math.h>

#define EDIM 128
#define NH 8
#define NB 2
#define TS 4096
#define HEDIM 1024   // NH*EDIM
#define BT 8192      // NB*TS

// Scratch (device globals; no runtime allocation)
__device__ __half g_Qh[(size_t)BT * HEDIM];
__device__ __half g_Kh[(size_t)BT * HEDIM];
__device__ __half g_Vh[(size_t)BT * HEDIM];
__device__ float  g_Op[(size_t)BT * HEDIM];

// ---------------------------------------------------------------------------
// fp32 GEMM, fp16 epilogue with scale: C = h16(scale * A@B).
// ---------------------------------------------------------------------------
__global__ __launch_bounds__(256) void gemm_h16s(const float* __restrict__ A,
                                                 const float* __restrict__ B,
                                                 __half* __restrict__ C,
                                                 int M, int N, int K,
                                                 float scale) {
    __shared__ float sA[64][33];
    __shared__ float sB[32][64];
    const int tid = threadIdx.x;
    const int tx = tid & 15, ty = tid >> 4;
    const int n0 = blockIdx.x << 6, m0 = blockIdx.y << 6;
    float acc[4][4] = {};
    for (int k0 = 0; k0 < K; k0 += 32) {
#pragma unroll
        for (int i = 0; i < 8; ++i) {
            int idx = tid + (i << 8);
            int r = idx >> 5, c = idx & 31;
            sA[r][c] = A[(size_t)(m0 + r) * K + (k0 + c)];
        }
#pragma unroll
        for (int i = 0; i < 8; ++i) {
            int idx = tid + (i << 8);
            int r = idx >> 6, c = idx & 63;
            sB[r][c] = B[(size_t)(k0 + r) * N + (n0 + c)];
        }
        __syncthreads();
#pragma unroll
        for (int kk = 0; kk < 32; ++kk) {
            float a0 = sA[(ty << 2) + 0][kk];
            float a1 = sA[(ty << 2) + 1][kk];
            float a2 = sA[(ty << 2) + 2][kk];
            float a3 = sA[(ty << 2) + 3][kk];
            float4 b4 = *(const float4*)&sB[kk][tx << 2];
            acc[0][0] += a0 * b4.x; acc[0][1] += a0 * b4.y;
            acc[0][2] += a0 * b4.z; acc[0][3] += a0 * b4.w;
            acc[1][0] += a1 * b4.x; acc[1][1] += a1 * b4.y;
            acc[1][2] += a1 * b4.z; acc[1][3] += a1 * b4.w;
            acc[2][0] += a2 * b4.x; acc[2][1] += a2 * b4.y;
            acc[2][2] += a2 * b4.z; acc[2][3] += a2 * b4.w;
            acc[3][0] += a3 * b4.x; acc[3][1] += a3 * b4.y;
            acc[3][2] += a3 * b4.z; acc[3][3] += a3 * b4.w;
        }
        __syncthreads();
    }
#pragma unroll
    for (int i = 0; i < 4; ++i) {
        size_t base = (size_t)(m0 + (ty << 2) + i) * N + n0 + (tx << 2);
        *(__half2*)&C[base] =
            __floats2half2_rn(acc[i][0] * scale, acc[i][1] * scale);
        *(__half2*)&C[base + 2] =
            __floats2half2_rn(acc[i][2] * scale, acc[i][3] * scale);
    }
}

// fp32 GEMM (final output projection).
__global__ __launch_bounds__(256) void gemm_k(const float* __restrict__ A,
                                              const float* __restrict__ B,
                                              float* __restrict__ C,
                                              int M, int N, int K) {
    __shared__ float sA[64][33];
    __shared__ float sB[32][64];
    const int tid = threadIdx.x;
    const int tx = tid & 15, ty = tid >> 4;
    const int n0 = blockIdx.x << 6, m0 = blockIdx.y << 6;
    float acc[4][4] = {};
    for (int k0 = 0; k0 < K; k0 += 32) {
#pragma unroll
        for (int i = 0; i < 8; ++i) {
            int idx = tid + (i << 8);
            int r = idx >> 5, c = idx & 31;
            sA[r][c] = A[(size_t)(m0 + r) * K + (k0 + c)];
        }
#pragma unroll
        for (int i = 0; i < 8; ++i) {
            int idx = tid + (i << 8);
            int r = idx >> 6, c = idx & 63;
            sB[r][c] = B[(size_t)(k0 + r) * N + (n0 + c)];
        }
        __syncthreads();
#pragma unroll
        for (int kk = 0; kk < 32; ++kk) {
            float a0 = sA[(ty << 2) + 0][kk];
            float a1 = sA[(ty << 2) + 1][kk];
            float a2 = sA[(ty << 2) + 2][kk];
            float a3 = sA[(ty << 2) + 3][kk];
            float4 b4 = *(const float4*)&sB[kk][tx << 2];
            acc[0][0] += a0 * b4.x; acc[0][1] += a0 * b4.y;
            acc[0][2] += a0 * b4.z; acc[0][3] += a0 * b4.w;
            acc[1][0] += a1 * b4.x; acc[1][1] += a1 * b4.y;
            acc[1][2] += a1 * b4.z; acc[1][3] += a1 * b4.w;
            acc[2][0] += a2 * b4.x; acc[2][1] += a2 * b4.y;
            acc[2][2] += a2 * b4.z; acc[2][3] += a2 * b4.w;
            acc[3][0] += a3 * b4.x; acc[3][1] += a3 * b4.y;
            acc[3][2] += a3 * b4.z; acc[3][3] += a3 * b4.w;
        }
        __syncthreads();
    }
#pragma unroll
    for (int i = 0; i < 4; ++i)
#pragma unroll
        for (int j = 0; j < 4; ++j)
            C[(size_t)(m0 + (ty << 2) + i) * N + n0 + (tx << 2) + j] = acc[i][j];
}

// ---------------------------------------------------------------------------
// Flash attention (FA2 layout): 4 warps, each owns 16 full rows.
// P is register-resident; softmax warp-local; KV double-buffered cp.async.
// ---------------------------------------------------------------------------
#define BM 64
#define BN 64
#define NT (TS / BN)
#define STRH 136            // halves per row (272B; 272%128==16 -> ldsm ok)
#define STRB 272

#define HOFF_Q  0
#define HOFF_K0 (HOFF_Q  + BM * STRH)   // 8704
#define HOFF_V0 (HOFF_K0 + BN * STRH)   // 17408
#define HOFF_K1 (HOFF_V0 + BN * STRH)   // 26112
#define HOFF_V1 (HOFF_K1 + BN * STRH)   // 34816
#define HOFF_END (HOFF_V1 + BN * STRH)  // 43520
#define SM_BYTES (HOFF_END * 2)         // 87040

#define LDSM4(r0, r1, r2, r3, p)                                              \
    asm volatile("ldmatrix.sync.aligned.m8n8.x4.shared.b16 {%0,%1,%2,%3},[%4];" \
                 : "=r"(r0), "=r"(r1), "=r"(r2), "=r"(r3) : "r"(p))
#define LDSM4T(r0, r1, r2, r3, p)                                             \
    asm volatile("ldmatrix.sync.aligned.m8n8.x4.trans.shared.b16 {%0,%1,%2,%3},[%4];" \
                 : "=r"(r0), "=r"(r1), "=r"(r2), "=r"(r3) : "r"(p))

#define MMA16816(d, a0, a1, a2, a3, b0, b1)                                   \
    asm volatile(                                                             \
        "mma.sync.aligned.m16n8k16.row.col.f32.f16.f16.f32 "                  \
        "{%0,%1,%2,%3},{%4,%5,%6,%7},{%8,%9},{%0,%1,%2,%3};"                  \
        : "+f"(d[0]), "+f"(d[1]), "+f"(d[2]), "+f"(d[3])                      \
        : "r"(a0), "r"(a1), "r"(a2), "r"(a3), "r"(b0), "r"(b1))

#define CPA16(dst, src)                                                       \
    asm volatile("cp.async.cg.shared.global [%0], [%1], 16;" ::               \
                 "r"(dst), "l"(src))
#define CP_COMMIT() asm volatile("cp.async.commit_group;")
#define CP_WAIT1()  asm volatile("cp.async.wait_group 1;")
#define CP_WAIT0()  asm volatile("cp.async.wait_group 0;")

__device__ __forceinline__ float ex2f(float x) {
    float r;
    asm("ex2.approx.ftz.f32 %0, %1;" : "=f"(r) : "f"(x));
    return r;
}
__device__ __forceinline__ unsigned packh2(float a, float b) {
    __half2 h = __floats2half2_rn(a, b);
    return *(unsigned*)&h;
}

__global__ __launch_bounds__(128, 2) void flash_attn_fa2(
    const __half* __restrict__ Qg, const __half* __restrict__ Kg,
    const __half* __restrict__ Vg, float* __restrict__ Og) {
    extern __shared__ __align__(16) char smem[];

    const int tid = threadIdx.x;
    const int wid = tid >> 5;       // 0..3, owns rows wid*16..wid*16+15
    const int lane = tid & 31;
    const int g = lane >> 2;        // row-in-8
    const int tg = lane & 3;        // thread-in-group

    const int h = blockIdx.y, b = blockIdx.z;
    const int q0 = blockIdx.x * BM;

    const size_t bh_off = (size_t)b * TS * HEDIM + (size_t)h * EDIM;
    const __half* Qbh = Qg + bh_off;
    const __half* Kbh = Kg + bh_off;
    const __half* Vbh = Vg + bh_off;
    float* Obh = Og + bh_off;

    const unsigned sbase = (unsigned)__cvta_generic_to_shared(smem);
    // A-frag gather (Q): rows wid*16 + (lane&15), 16B col-chunk (lane>>4)
    const unsigned aQ0 = sbase + HOFF_Q * 2 +
        (wid * 16 + (lane & 15)) * STRB + (lane >> 4) * 16;
    // B-frag gather (K, non-trans): rows (lane&7)+((lane>>4)&1)*8
    const unsigned kpat =
        ((lane & 7) + ((lane >> 4) & 1) * 8) * STRB + ((lane >> 3) & 1) * 16;
    // B-frag gather (V, trans): k'-rows (lane&7)+((lane>>3)&1)*8, col 16B (lane>>4)
    const unsigned vpat =
        ((lane & 7) + ((lane >> 3) & 1) * 8) * STRB + (lane >> 4) * 16;
    const unsigned aK[2] = {sbase + HOFF_K0 * 2 + kpat,
                            sbase + HOFF_K1 * 2 + kpat};
    const unsigned aV[2] = {sbase + HOFF_V0 * 2 + vpat,
                            sbase + HOFF_V1 * 2 + vpat};

    // ---- group 0: Q tile + KV tile 0 (24 CPA16/thread) ----
    {
        const unsigned dQ = sbase + HOFF_Q * 2;
        const unsigned dK = sbase + HOFF_K0 * 2;
        const unsigned dV = sbase + HOFF_V0 * 2;
#pragma unroll
        for (int i = 0; i < 8; ++i) {
            int idx = tid + (i << 7);          // 0..1023
            int r = idx >> 4, c = idx & 15;
            const size_t goff = (size_t)r * HEDIM + c * 8;
            const unsigned soff = r * STRB + c * 16;
            CPA16(dQ + soff, Qbh + (size_t)q0 * HEDIM + goff);
            CPA16(dK + soff, Kbh + goff);
            CPA16(dV + soff, Vbh + goff);
        }
        CP_COMMIT();
    }

    const int row0 = wid * 16 + g;
    const int row1 = row0 + 8;

    float m0 = -INFINITY, m1 = -INFINITY, l0s = 0.f, l1s = 0.f;
    float o[16][4];
#pragma unroll
    for (int nb = 0; nb < 16; ++nb)
#pragma unroll
        for (int j = 0; j < 4; ++j) o[nb][j] = 0.f;

    unsigned qf[8][4];  // persistent Q fragments (k = 0..127)

    for (int n = 0; n < NT; ++n) {
        const int buf = n & 1;
        // ---- prefetch KV tile n+1 into the other buffer ----
        if (n + 1 < NT) {
            const unsigned dK = sbase + (buf ? HOFF_K0 : HOFF_K1) * 2;
            const unsigned dV = sbase + (buf ? HOFF_V0 : HOFF_V1) * 2;
            const size_t kvg = (size_t)(n + 1) * BN * HEDIM;
#pragma unroll
            for (int i = 0; i < 8; ++i) {
                int idx = tid + (i << 7);
                int r = idx >> 4, c = idx & 15;
                const size_t goff = kvg + (size_t)r * HEDIM + c * 8;
                const unsigned soff = r * STRB + c * 16;
                CPA16(dK + soff, Kbh + goff);
                CPA16(dV + soff, Vbh + goff);
            }
            CP_COMMIT();
            CP_WAIT1();   // tile n's group done
        } else {
            CP_WAIT0();
        }
        __syncthreads();  // all threads' copies of tile n visible

        if (n == 0) {     // preload Q fragments once
#pragma unroll
            for (int ks = 0; ks < 8; ++ks)
                LDSM4(qf[ks][0], qf[ks][1], qf[ks][2], qf[ks][3],
                      aQ0 + ks * 32);
        }

        // ---- S = Q @ K^T over full 64 cols ----
        float s[8][4];
#pragma unroll
        for (int nb = 0; nb < 8; ++nb)
#pragma unroll
            for (int j = 0; j < 4; ++j) s[nb][j] = 0.f;

        unsigned ak = aK[buf];
#pragma unroll
        for (int ks = 0; ks < 8; ++ks) {
#pragma unroll
            for (int nb2 = 0; nb2 < 4; ++nb2) {
                unsigned b0, b1, b2, b3;
                LDSM4(b0, b1, b2, b3, ak + nb2 * 16 * STRB);
                MMA16816(s[nb2 * 2 + 0], qf[ks][0], qf[ks][1], qf[ks][2],
                         qf[ks][3], b0, b1);
                MMA16816(s[nb2 * 2 + 1], qf[ks][0], qf[ks][1], qf[ks][2],
                         qf[ks][3], b2, b3);
            }
            ak += 32;
        }

        // ---- warp-local online softmax (base-2; scale folded upstream) ----
        float mx0 = -INFINITY, mx1 = -INFINITY;
#pragma unroll
        for (int nb = 0; nb < 8; ++nb) {
            mx0 = fmaxf(mx0, fmaxf(s[nb][0], s[nb][1]));
            mx1 = fmaxf(mx1, fmaxf(s[nb][2], s[nb][3]));
        }
        mx0 = fmaxf(mx0, __shfl_xor_sync(0xffffffffu, mx0, 1));
        mx0 = fmaxf(mx0, __shfl_xor_sync(0xffffffffu, mx0, 2));
        mx1 = fmaxf(mx1, __shfl_xor_sync(0xffffffffu, mx1, 1));
        mx1 = fmaxf(mx1, __shfl_xor_sync(0xffffffffu, mx1, 2));
        const float mn0 = fmaxf(m0, mx0), mn1 = fmaxf(m1, mx1);
        const float al0 = ex2f(m0 - mn0), al1 = ex2f(m1 - mn1);
        m0 = mn0; m1 = mn1;

        float ps0 = 0.f, ps1 = 0.f;
        unsigned ph[8][2];
#pragma unroll
        for (int nb = 0; nb < 8; ++nb) {
            s[nb][0] = ex2f(s[nb][0] - mn0);
            s[nb][1] = ex2f(s[nb][1] - mn0);
            s[nb][2] = ex2f(s[nb][2] - mn1);
            s[nb][3] = ex2f(s[nb][3] - mn1);
            ps0 += s[nb][0] + s[nb][1];
            ps1 += s[nb][2] + s[nb][3];
            ph[nb][0] = packh2(s[nb][0], s[nb][1]);   // row g
            ph[nb][1] = packh2(s[nb][2], s[nb][3]);   // row g+8
        }
        ps0 += __shfl_xor_sync(0xffffffffu, ps0, 1);
        ps0 += __shfl_xor_sync(0xffffffffu, ps0, 2);
        ps1 += __shfl_xor_sync(0xffffffffu, ps1, 1);
        ps1 += __shfl_xor_sync(0xffffffffu, ps1, 2);
        l0s = l0s * al0 + ps0;
        l1s = l1s * al1 + ps1;

        // rescale O
#pragma unroll
        for (int nb = 0; nb < 16; ++nb) {
            o[nb][0] *= al0; o[nb][1] *= al0;
            o[nb][2] *= al1; o[nb][3] *= al1;
        }

        // ---- O += P @ V (P from registers; full 128 cols) ----
        unsigned av0 = aV[buf];
#pragma unroll
        for (int ks = 0; ks < 4; ++ks) {
            const unsigned pa0 = ph[2 * ks][0], pa1 = ph[2 * ks][1];
            const unsigned pa2 = ph[2 * ks + 1][0], pa3 = ph[2 * ks + 1][1];
            unsigned av = av0;
#pragma unroll
            for (int np = 0; np < 8; ++np) {
                unsigned v0, v1, v2, v3;
                LDSM4T(v0, v1, v2, v3, av);
                MMA16816(o[np * 2 + 0], pa0, pa1, pa2, pa3, v0, v1);
                MMA16816(o[np * 2 + 1], pa0, pa1, pa2, pa3, v2, v3);
                av += 32;
            }
            av0 += 16 * STRB;
        }
        __syncthreads();  // all warps done reading this buf before overwrite
    }

    // ---- normalize + write O ----
    const float inv0 = 1.f / l0s, inv1 = 1.f / l1s;
#pragma unroll
    for (int nb = 0; nb < 16; ++nb) {
        const int col = nb * 8 + 2 * tg;
        float2 r0v = make_float2(o[nb][0] * inv0, o[nb][1] * inv0);
        float2 r1v = make_float2(o[nb][2] * inv1, o[nb][3] * inv1);
        *(float2*)&Obh[(size_t)(q0 + row0) * HEDIM + col] = r0v;
        *(float2*)&Obh[(size_t)(q0 + row1) * HEDIM + col] = r1v;
    }
}

// ---------------------------------------------------------------------------
extern "C" void kernel_launch(void* const* d_in, const int* in_sizes, int n_in,
                              void* d_out, int out_size) {
    (void)in_sizes; (void)n_in; (void)out_size;
    const float* k  = (const float*)d_in[0];
    const float* q  = (const float*)d_in[1];
    const float* v  = (const float*)d_in[2];
    const float* Wk = (const float*)d_in[3];
    const float* Wq = (const float*)d_in[4];
    const float* Wv = (const float*)d_in[5];
    const float* Wu = (const float*)d_in[6];
    float* out = (float*)d_out;

    __half *gQ, *gK, *gV;
    float* gO;
    cudaGetSymbolAddress((void**)&gQ, g_Qh);
    cudaGetSymbolAddress((void**)&gK, g_Kh);
    cudaGetSymbolAddress((void**)&gV, g_Vh);
    cudaGetSymbolAddress((void**)&gO, g_Op);

    cudaFuncSetAttribute(flash_attn_fa2,
                         cudaFuncAttributeMaxDynamicSharedMemorySize, SM_BYTES);

    // log2(e)/sqrt(128) folded into Q projection (softmax runs in base 2)
    const float qscale = 0.12751744f;
    dim3 blk(256);
    dim3 gproj(HEDIM / 64, BT / 64);
    gemm_h16s<<<gproj, blk>>>(q, Wq, gQ, BT, HEDIM, EDIM, qscale);
    gemm_h16s<<<gproj, blk>>>(k, Wk, gK, BT, HEDIM, EDIM, 1.0f);
    gemm_h16s<<<gproj, blk>>>(v, Wv, gV, BT, HEDIM, EDIM, 1.0f);

    dim3 gatt(TS / BM, NH, NB);
    flash_attn_fa2<<<gatt, dim3(128), SM_BYTES>>>(gQ, gK, gV, gO);

    dim3 gout(EDIM / 64, BT / 64);
    gemm_k<<<gout, blk>>>(gO, Wu, out, BT, EDIM, HEDIM);
}